// round 1
// baseline (speedup 1.0000x reference)
#include <cuda_runtime.h>
#include <cuda_bf16.h>
#include <math.h>

#define N_NODES 10000
#define N_EDGES 320000
#define H 128
#define NODE_IN 64
#define EDGE_IN 16
#define L_LAYERS 4
#define EPS_F 1e-8f
#define TILE 32

// ---------------- scratch (device globals; no allocation allowed) ----------------
__device__ float g_temb[H];
__device__ float g_hfeat[N_NODES * H];
__device__ float g_efeat[(size_t)N_EDGES * H];   // 164 MB
__device__ float g_C[(size_t)N_EDGES * H];       // 164 MB
__device__ float g_A[N_NODES * H];
__device__ float g_B[N_NODES * H];
__device__ float g_x[N_NODES * 3];
__device__ float g_aggm[N_NODES * H];
__device__ float g_aggx[N_NODES * 3];

__device__ __forceinline__ float silu_f(float v) {
    return v / (1.0f + __expf(-v));
}

// ---------------- t embedding: 1x128 ----------------
__global__ void time_emb_kernel(const float* __restrict__ t,
                                const float* __restrict__ w1, const float* __restrict__ b1,
                                const float* __restrict__ w2, const float* __restrict__ b2,
                                float* __restrict__ temb) {
    __shared__ float h1[H];
    int k = threadIdx.x;
    h1[k] = silu_f(t[0] * w1[k] + b1[k]);
    __syncthreads();
    float acc = b2[k];
    #pragma unroll 4
    for (int j = 0; j < H; j++) acc = fmaf(h1[j], w2[j * H + k], acc);
    temb[k] = acc;
}

// ---------------- node embedding + x init ----------------
__global__ void node_embed_kernel(const float* __restrict__ h,
                                  const float* __restrict__ W, const float* __restrict__ b,
                                  const float* __restrict__ temb,
                                  const float* __restrict__ x_in,
                                  float* __restrict__ hf, float* __restrict__ xb) {
    __shared__ float hs[NODE_IN];
    int i = blockIdx.x, k = threadIdx.x;
    if (k < NODE_IN) hs[k] = h[i * NODE_IN + k];
    __syncthreads();
    float acc = b[k] + temb[k];
    #pragma unroll
    for (int j = 0; j < NODE_IN; j += 4) {
        float4 v = *reinterpret_cast<const float4*>(&hs[j]);
        acc = fmaf(v.x, W[(j + 0) * H + k], acc);
        acc = fmaf(v.y, W[(j + 1) * H + k], acc);
        acc = fmaf(v.z, W[(j + 2) * H + k], acc);
        acc = fmaf(v.w, W[(j + 3) * H + k], acc);
    }
    hf[i * H + k] = acc;
    if (k < 3) xb[i * 3 + k] = x_in[i * 3 + k];
}

// ---------------- edge embedding: E x 16 -> E x 128 ----------------
__global__ void edge_embed_kernel(const float* __restrict__ ea,
                                  const float* __restrict__ W, const float* __restrict__ b,
                                  float* __restrict__ ef) {
    __shared__ float eas[TILE][EDGE_IN];
    int k = threadIdx.x;
    size_t e0 = (size_t)blockIdx.x * TILE;
    for (int i = k; i < TILE * EDGE_IN; i += 128)
        eas[i / EDGE_IN][i % EDGE_IN] = ea[e0 * EDGE_IN + i];
    __syncthreads();
    float bk = b[k];
    for (int e = 0; e < TILE; e++) {
        float acc = bk;
        #pragma unroll
        for (int j = 0; j < EDGE_IN; j++) acc = fmaf(eas[e][j], W[j * H + k], acc);
        ef[(e0 + e) * H + k] = acc;
    }
}

// ---------------- per-layer: A = hf@W1a, B = hf@W1b ----------------
__global__ void ab_kernel(const float* __restrict__ hf, const float* __restrict__ w1,
                          float* __restrict__ A, float* __restrict__ B) {
    __shared__ float hs[H];
    int i = blockIdx.x, k = threadIdx.x;
    hs[k] = hf[i * H + k];
    __syncthreads();
    float a = 0.f, b = 0.f;
    for (int j = 0; j < H; j += 4) {
        float4 v = *reinterpret_cast<const float4*>(&hs[j]);
        a = fmaf(v.x, w1[(j + 0) * H + k], a);
        a = fmaf(v.y, w1[(j + 1) * H + k], a);
        a = fmaf(v.z, w1[(j + 2) * H + k], a);
        a = fmaf(v.w, w1[(j + 3) * H + k], a);
        b = fmaf(v.x, w1[(H + j + 0) * H + k], b);
        b = fmaf(v.y, w1[(H + j + 1) * H + k], b);
        b = fmaf(v.z, w1[(H + j + 2) * H + k], b);
        b = fmaf(v.w, w1[(H + j + 3) * H + k], b);
    }
    A[i * H + k] = a;
    B[i * H + k] = b;
}

// ---------------- per-layer: C = edge_feat @ W1c + b1 ----------------
__global__ void __launch_bounds__(128) c_kernel(const float* __restrict__ ef,
                         const float* __restrict__ W, const float* __restrict__ b1,
                         float* __restrict__ C) {
    __shared__ float efs[TILE][H];
    int k = threadIdx.x;
    size_t e0 = (size_t)blockIdx.x * TILE;
    #pragma unroll 4
    for (int e = 0; e < TILE; e++) efs[e][k] = ef[(e0 + e) * H + k];
    __syncthreads();
    float acc[TILE];
    #pragma unroll
    for (int e = 0; e < TILE; e++) acc[e] = 0.f;
    for (int j = 0; j < H; j += 4) {
        float w0 = W[(j + 0) * H + k];
        float w1v = W[(j + 1) * H + k];
        float w2v = W[(j + 2) * H + k];
        float w3 = W[(j + 3) * H + k];
        #pragma unroll
        for (int e = 0; e < TILE; e++) {
            float4 v = *reinterpret_cast<const float4*>(&efs[e][j]);
            acc[e] = fmaf(v.x, w0, acc[e]);
            acc[e] = fmaf(v.y, w1v, acc[e]);
            acc[e] = fmaf(v.z, w2v, acc[e]);
            acc[e] = fmaf(v.w, w3, acc[e]);
        }
    }
    float bk = b1[k];
    #pragma unroll 4
    for (int e = 0; e < TILE; e++) C[(e0 + e) * H + k] = acc[e] + bk;
}

// ---------------- per-layer fused edge kernel ----------------
__global__ void __launch_bounds__(128) edge_kernel(
    const int* __restrict__ row, const int* __restrict__ col,
    const float* __restrict__ x,
    const float* __restrict__ A, const float* __restrict__ Bm,
    const float* __restrict__ C, const float* __restrict__ w1d,
    const float* __restrict__ w2, const float* __restrict__ b2,
    const float* __restrict__ c1, const float* __restrict__ cb,
    const float* __restrict__ c2,
    float* __restrict__ aggm, float* __restrict__ aggx) {
    __shared__ float hid[TILE][H];     // hidden -> m -> cv*c2k reuse
    __shared__ float dsq_s[TILE];
    __shared__ float diff_s[TILE][3];
    __shared__ int row_s[TILE];
    __shared__ int col_s[TILE];
    int k = threadIdx.x;
    int e0 = blockIdx.x * TILE;

    if (k < TILE) {
        int e = e0 + k;
        int r = row[e], c = col[e];
        row_s[k] = r; col_s[k] = c;
        float dx = x[r * 3 + 0] - x[c * 3 + 0];
        float dy = x[r * 3 + 1] - x[c * 3 + 1];
        float dz = x[r * 3 + 2] - x[c * 3 + 2];
        diff_s[k][0] = dx; diff_s[k][1] = dy; diff_s[k][2] = dz;
        dsq_s[k] = dx * dx + dy * dy + dz * dz;
    }
    __syncthreads();

    // hidden = silu(A[row] + B[col] + dsq*w1d + C)
    float w1dk = w1d[k];
    #pragma unroll 4
    for (int e = 0; e < TILE; e++) {
        int r = row_s[e], c = col_s[e];
        float pre = A[r * H + k] + Bm[c * H + k]
                  + C[((size_t)(e0 + e)) * H + k] + dsq_s[e] * w1dk;
        hid[e][k] = silu_f(pre);
    }
    __syncthreads();

    // GEMM1: m = silu(hidden @ w2 + b2)
    float acc[TILE];
    #pragma unroll
    for (int e = 0; e < TILE; e++) acc[e] = 0.f;
    for (int j = 0; j < H; j += 4) {
        float w0 = w2[(j + 0) * H + k];
        float w1v = w2[(j + 1) * H + k];
        float w2v = w2[(j + 2) * H + k];
        float w3 = w2[(j + 3) * H + k];
        #pragma unroll
        for (int e = 0; e < TILE; e++) {
            float4 v = *reinterpret_cast<const float4*>(&hid[e][j]);
            acc[e] = fmaf(v.x, w0, acc[e]);
            acc[e] = fmaf(v.y, w1v, acc[e]);
            acc[e] = fmaf(v.z, w2v, acc[e]);
            acc[e] = fmaf(v.w, w3, acc[e]);
        }
    }
    float b2k = b2[k];
    __syncthreads();   // all reads of hid done
    #pragma unroll 4
    for (int e = 0; e < TILE; e++) {
        float m = silu_f(acc[e] + b2k);
        hid[e][k] = m;
        atomicAdd(&aggm[(size_t)row_s[e] * H + k], m);
    }
    __syncthreads();

    // GEMM2: cv = silu(m @ c1 + cb)
    #pragma unroll
    for (int e = 0; e < TILE; e++) acc[e] = 0.f;
    for (int j = 0; j < H; j += 4) {
        float w0 = c1[(j + 0) * H + k];
        float w1v = c1[(j + 1) * H + k];
        float w2v = c1[(j + 2) * H + k];
        float w3 = c1[(j + 3) * H + k];
        #pragma unroll
        for (int e = 0; e < TILE; e++) {
            float4 v = *reinterpret_cast<const float4*>(&hid[e][j]);
            acc[e] = fmaf(v.x, w0, acc[e]);
            acc[e] = fmaf(v.y, w1v, acc[e]);
            acc[e] = fmaf(v.z, w2v, acc[e]);
            acc[e] = fmaf(v.w, w3, acc[e]);
        }
    }
    float cbk = cb[k], c2k = c2[k];
    __syncthreads();   // all reads of hid (m) done
    #pragma unroll 4
    for (int e = 0; e < TILE; e++) {
        float cv = silu_f(acc[e] + cbk);
        hid[e][k] = cv * c2k;
    }
    __syncthreads();

    // per-edge reduction of cv*c2 over k, then trans atomics
    int warp = k >> 5, lane = k & 31;
    #pragma unroll
    for (int e = warp * 8; e < warp * 8 + 8; e++) {
        float s = hid[e][lane] + hid[e][lane + 32] + hid[e][lane + 64] + hid[e][lane + 96];
        #pragma unroll
        for (int off = 16; off; off >>= 1) s += __shfl_xor_sync(0xffffffffu, s, off);
        if (lane == 0) {
            float wv = tanhf(s);
            float dist = sqrtf(dsq_s[e] + EPS_F);
            float inv = wv / (dist + EPS_F);
            int r = row_s[e];
            atomicAdd(&aggx[r * 3 + 0], diff_s[e][0] * inv);
            atomicAdd(&aggx[r * 3 + 1], diff_s[e][1] * inv);
            atomicAdd(&aggx[r * 3 + 2], diff_s[e][2] * inv);
        }
    }
}

// ---------------- per-layer node update ----------------
__global__ void node_update_kernel(float* __restrict__ hf, const float* __restrict__ aggm,
                                   float* __restrict__ xb, const float* __restrict__ aggx,
                                   const float* __restrict__ mask,
                                   const float* __restrict__ n1, const float* __restrict__ nb1,
                                   const float* __restrict__ n2, const float* __restrict__ nb2) {
    __shared__ float ins[2 * H];
    __shared__ float hid[H];
    int i = blockIdx.x, k = threadIdx.x;
    float hfk = hf[i * H + k];
    ins[k] = hfk;
    ins[H + k] = aggm[i * H + k];
    __syncthreads();
    float a = nb1[k];
    for (int j = 0; j < 2 * H; j += 4) {
        float4 v = *reinterpret_cast<const float4*>(&ins[j]);
        a = fmaf(v.x, n1[(j + 0) * H + k], a);
        a = fmaf(v.y, n1[(j + 1) * H + k], a);
        a = fmaf(v.z, n1[(j + 2) * H + k], a);
        a = fmaf(v.w, n1[(j + 3) * H + k], a);
    }
    hid[k] = silu_f(a);
    __syncthreads();
    float b = nb2[k];
    for (int j = 0; j < H; j += 4) {
        float4 v = *reinterpret_cast<const float4*>(&hid[j]);
        b = fmaf(v.x, n2[(j + 0) * H + k], b);
        b = fmaf(v.y, n2[(j + 1) * H + k], b);
        b = fmaf(v.z, n2[(j + 2) * H + k], b);
        b = fmaf(v.w, n2[(j + 3) * H + k], b);
    }
    hf[i * H + k] = hfk + b;
    if (k < 3) xb[i * 3 + k] += aggx[i * 3 + k] * mask[i];
}

// ---------------- final velocity ----------------
__global__ void v_kernel(const float* __restrict__ xb, const float* __restrict__ x_in,
                         const float* __restrict__ mask, float* __restrict__ out) {
    int idx = blockIdx.x * blockDim.x + threadIdx.x;
    if (idx < N_NODES * 3) {
        int i = idx / 3;
        out[idx] = (xb[idx] - x_in[idx]) * mask[i];
    }
}

extern "C" void kernel_launch(void* const* d_in, const int* in_sizes, int n_in,
                              void* d_out, int out_size) {
    const float* h        = (const float*)d_in[0];
    const float* x        = (const float*)d_in[1];
    const int*   ei       = (const int*)d_in[2];
    const float* ea       = (const float*)d_in[3];
    const float* t        = (const float*)d_in[4];
    const float* mask     = (const float*)d_in[5];
    const float* tw1      = (const float*)d_in[6];
    const float* tb1      = (const float*)d_in[7];
    const float* tw2      = (const float*)d_in[8];
    const float* tb2      = (const float*)d_in[9];
    const float* new_     = (const float*)d_in[10];
    const float* neb      = (const float*)d_in[11];
    const float* eew      = (const float*)d_in[12];
    const float* eeb      = (const float*)d_in[13];
    const float* ew1      = (const float*)d_in[14];
    const float* eb1      = (const float*)d_in[15];
    const float* ew2      = (const float*)d_in[16];
    const float* eb2      = (const float*)d_in[17];
    const float* cw1      = (const float*)d_in[18];
    const float* cb1      = (const float*)d_in[19];
    const float* cw2      = (const float*)d_in[20];
    const float* nw1      = (const float*)d_in[21];
    const float* nb1      = (const float*)d_in[22];
    const float* nw2      = (const float*)d_in[23];
    const float* nb2      = (const float*)d_in[24];
    float* out = (float*)d_out;

    float *temb, *hfeat, *efeat, *Cb, *Ab, *Bb, *xb, *aggm, *aggx;
    cudaGetSymbolAddress((void**)&temb,  g_temb);
    cudaGetSymbolAddress((void**)&hfeat, g_hfeat);
    cudaGetSymbolAddress((void**)&efeat, g_efeat);
    cudaGetSymbolAddress((void**)&Cb,    g_C);
    cudaGetSymbolAddress((void**)&Ab,    g_A);
    cudaGetSymbolAddress((void**)&Bb,    g_B);
    cudaGetSymbolAddress((void**)&xb,    g_x);
    cudaGetSymbolAddress((void**)&aggm,  g_aggm);
    cudaGetSymbolAddress((void**)&aggx,  g_aggx);

    time_emb_kernel<<<1, H>>>(t, tw1, tb1, tw2, tb2, temb);
    node_embed_kernel<<<N_NODES, H>>>(h, new_, neb, temb, x, hfeat, xb);
    edge_embed_kernel<<<N_EDGES / TILE, H>>>(ea, eew, eeb, efeat);

    for (int l = 0; l < L_LAYERS; l++) {
        const float* w1  = ew1 + (size_t)l * 385 * H;
        const float* b1  = eb1 + l * H;
        const float* w2  = ew2 + (size_t)l * H * H;
        const float* b2  = eb2 + l * H;
        const float* c1  = cw1 + (size_t)l * H * H;
        const float* cb  = cb1 + l * H;
        const float* c2  = cw2 + l * H;
        const float* n1  = nw1 + (size_t)l * 2 * H * H;
        const float* nb1l = nb1 + l * H;
        const float* n2  = nw2 + (size_t)l * H * H;
        const float* nb2l = nb2 + l * H;

        ab_kernel<<<N_NODES, H>>>(hfeat, w1, Ab, Bb);
        c_kernel<<<N_EDGES / TILE, H>>>(efeat, w1 + 257 * H, b1, Cb);
        cudaMemsetAsync(aggm, 0, (size_t)N_NODES * H * sizeof(float));
        cudaMemsetAsync(aggx, 0, (size_t)N_NODES * 3 * sizeof(float));
        edge_kernel<<<N_EDGES / TILE, H>>>(ei, ei + N_EDGES, xb, Ab, Bb, Cb,
                                           w1 + 256 * H, w2, b2, c1, cb, c2,
                                           aggm, aggx);
        node_update_kernel<<<N_NODES, H>>>(hfeat, aggm, xb, aggx, mask,
                                           n1, nb1l, n2, nb2l);
    }
    v_kernel<<<(N_NODES * 3 + 127) / 128, 128>>>(xb, x, mask, out);
}

// round 2
// speedup vs baseline: 1.3977x; 1.3977x over previous
#include <cuda_runtime.h>
#include <cuda_bf16.h>
#include <math.h>

#define N_NODES 10000
#define N_EDGES 320000
#define H 128
#define NODE_IN 64
#define EDGE_IN 16
#define L_LAYERS 4
#define EPS_F 1e-8f
#define TILE 32

// ---------------- scratch (device globals; no allocation allowed) ----------------
__device__ float g_temb[H];
__device__ float g_hfeat[N_NODES * H];
__device__ float g_A[N_NODES * H];
__device__ float g_B[N_NODES * H];
__device__ float g_x[N_NODES * 3];
__device__ float g_aggm[N_NODES * H];
__device__ float g_aggx[N_NODES * 3];
__device__ float g_M[EDGE_IN * H];   // folded low-rank edge weight for current layer
__device__ float g_c0[H];            // folded bias for current layer

__device__ __forceinline__ float silu_f(float v) {
    return v / (1.0f + __expf(-v));
}

// ---------------- t embedding: 1x128 ----------------
__global__ void time_emb_kernel(const float* __restrict__ t,
                                const float* __restrict__ w1, const float* __restrict__ b1,
                                const float* __restrict__ w2, const float* __restrict__ b2,
                                float* __restrict__ temb) {
    __shared__ float h1[H];
    int k = threadIdx.x;
    h1[k] = silu_f(t[0] * w1[k] + b1[k]);
    __syncthreads();
    float acc = b2[k];
    #pragma unroll 4
    for (int j = 0; j < H; j++) acc = fmaf(h1[j], w2[j * H + k], acc);
    temb[k] = acc;
}

// ---------------- node embedding + x init ----------------
__global__ void node_embed_kernel(const float* __restrict__ h,
                                  const float* __restrict__ W, const float* __restrict__ b,
                                  const float* __restrict__ temb,
                                  const float* __restrict__ x_in,
                                  float* __restrict__ hf, float* __restrict__ xb) {
    __shared__ float hs[NODE_IN];
    int i = blockIdx.x, k = threadIdx.x;
    if (k < NODE_IN) hs[k] = h[i * NODE_IN + k];
    __syncthreads();
    float acc = b[k] + temb[k];
    #pragma unroll
    for (int j = 0; j < NODE_IN; j += 4) {
        float4 v = *reinterpret_cast<const float4*>(&hs[j]);
        acc = fmaf(v.x, W[(j + 0) * H + k], acc);
        acc = fmaf(v.y, W[(j + 1) * H + k], acc);
        acc = fmaf(v.z, W[(j + 2) * H + k], acc);
        acc = fmaf(v.w, W[(j + 3) * H + k], acc);
    }
    hf[i * H + k] = acc;
    if (k < 3) xb[i * 3 + k] = x_in[i * 3 + k];
}

// ---------------- per-layer: fold M = Wee @ W1c (16x128), c0 = beb@W1c + b1 ----------------
__global__ void prep_kernel(const float* __restrict__ eew, const float* __restrict__ eeb,
                            const float* __restrict__ w1c, const float* __restrict__ b1,
                            float* __restrict__ M, float* __restrict__ c0) {
    __shared__ float es[EDGE_IN][H];
    __shared__ float ebs[H];
    int k = threadIdx.x;
    #pragma unroll
    for (int i = 0; i < EDGE_IN; i++) es[i][k] = eew[i * H + k];
    ebs[k] = eeb[k];
    __syncthreads();
    float m[EDGE_IN];
    #pragma unroll
    for (int i = 0; i < EDGE_IN; i++) m[i] = 0.f;
    float c = b1[k];
    for (int j = 0; j < H; j++) {
        float w = w1c[j * H + k];
        c = fmaf(ebs[j], w, c);
        #pragma unroll
        for (int i = 0; i < EDGE_IN; i++) m[i] = fmaf(es[i][j], w, m[i]);
    }
    #pragma unroll
    for (int i = 0; i < EDGE_IN; i++) M[i * H + k] = m[i];
    c0[k] = c;
}

// ---------------- per-layer: A = hf@W1a, B = hf@W1b; also zero agg buffers ----------------
__global__ void ab_kernel(const float* __restrict__ hf, const float* __restrict__ w1,
                          float* __restrict__ A, float* __restrict__ B,
                          float* __restrict__ aggm, float* __restrict__ aggx) {
    __shared__ float hs[H];
    int i = blockIdx.x, k = threadIdx.x;
    hs[k] = hf[i * H + k];
    __syncthreads();
    float a = 0.f, b = 0.f;
    for (int j = 0; j < H; j += 4) {
        float4 v = *reinterpret_cast<const float4*>(&hs[j]);
        a = fmaf(v.x, w1[(j + 0) * H + k], a);
        a = fmaf(v.y, w1[(j + 1) * H + k], a);
        a = fmaf(v.z, w1[(j + 2) * H + k], a);
        a = fmaf(v.w, w1[(j + 3) * H + k], a);
        b = fmaf(v.x, w1[(H + j + 0) * H + k], b);
        b = fmaf(v.y, w1[(H + j + 1) * H + k], b);
        b = fmaf(v.z, w1[(H + j + 2) * H + k], b);
        b = fmaf(v.w, w1[(H + j + 3) * H + k], b);
    }
    A[i * H + k] = a;
    B[i * H + k] = b;
    aggm[i * H + k] = 0.f;
    if (k < 3) aggx[i * 3 + k] = 0.f;
}

// ---------------- per-layer fused edge kernel (C folded in, low-rank) ----------------
__global__ void __launch_bounds__(128) edge_kernel(
    const int* __restrict__ row, const int* __restrict__ col,
    const float* __restrict__ x,
    const float* __restrict__ A, const float* __restrict__ Bm,
    const float* __restrict__ ea,
    const float* __restrict__ M, const float* __restrict__ c0,
    const float* __restrict__ w1d,
    const float* __restrict__ w2, const float* __restrict__ b2,
    const float* __restrict__ c1, const float* __restrict__ cb,
    const float* __restrict__ c2,
    float* __restrict__ aggm, float* __restrict__ aggx) {
    __shared__ float hid[TILE][H];     // hidden -> m -> cv*c2k reuse
    __shared__ float Ms[EDGE_IN * H];  // 8KB folded weight
    __shared__ float eas[TILE][EDGE_IN];
    __shared__ float dsq_s[TILE];
    __shared__ float diff_s[TILE][3];
    __shared__ int row_s[TILE];
    __shared__ int col_s[TILE];
    int k = threadIdx.x;
    int e0 = blockIdx.x * TILE;

    // cooperative loads
    #pragma unroll
    for (int i = 0; i < EDGE_IN; i++) Ms[i * H + k] = M[i * H + k];
    {
        // ea tile: 32 edges x 16 = 512 floats = 128 float4
        float4 v = reinterpret_cast<const float4*>(ea + (size_t)e0 * EDGE_IN)[k];
        reinterpret_cast<float4*>(&eas[0][0])[k] = v;
    }
    if (k < TILE) {
        int e = e0 + k;
        int r = row[e], c = col[e];
        row_s[k] = r; col_s[k] = c;
        float dx = x[r * 3 + 0] - x[c * 3 + 0];
        float dy = x[r * 3 + 1] - x[c * 3 + 1];
        float dz = x[r * 3 + 2] - x[c * 3 + 2];
        diff_s[k][0] = dx; diff_s[k][1] = dy; diff_s[k][2] = dz;
        dsq_s[k] = dx * dx + dy * dy + dz * dz;
    }
    __syncthreads();

    // hidden = silu(A[row] + B[col] + dsq*w1d + ea@M + c0)
    float w1dk = w1d[k];
    float c0k = c0[k];
    #pragma unroll 2
    for (int e = 0; e < TILE; e++) {
        int r = row_s[e], c = col_s[e];
        float pre = A[r * H + k] + Bm[c * H + k] + c0k + dsq_s[e] * w1dk;
        #pragma unroll
        for (int i = 0; i < EDGE_IN; i += 4) {
            float4 v = *reinterpret_cast<const float4*>(&eas[e][i]);
            pre = fmaf(v.x, Ms[(i + 0) * H + k], pre);
            pre = fmaf(v.y, Ms[(i + 1) * H + k], pre);
            pre = fmaf(v.z, Ms[(i + 2) * H + k], pre);
            pre = fmaf(v.w, Ms[(i + 3) * H + k], pre);
        }
        hid[e][k] = silu_f(pre);
    }
    __syncthreads();

    // GEMM1: m = silu(hidden @ w2 + b2)
    float acc[TILE];
    #pragma unroll
    for (int e = 0; e < TILE; e++) acc[e] = 0.f;
    for (int j = 0; j < H; j += 4) {
        float w0 = w2[(j + 0) * H + k];
        float w1v = w2[(j + 1) * H + k];
        float w2v = w2[(j + 2) * H + k];
        float w3 = w2[(j + 3) * H + k];
        #pragma unroll
        for (int e = 0; e < TILE; e++) {
            float4 v = *reinterpret_cast<const float4*>(&hid[e][j]);
            acc[e] = fmaf(v.x, w0, acc[e]);
            acc[e] = fmaf(v.y, w1v, acc[e]);
            acc[e] = fmaf(v.z, w2v, acc[e]);
            acc[e] = fmaf(v.w, w3, acc[e]);
        }
    }
    float b2k = b2[k];
    __syncthreads();   // all reads of hid done
    #pragma unroll 4
    for (int e = 0; e < TILE; e++) {
        float m = silu_f(acc[e] + b2k);
        hid[e][k] = m;
        atomicAdd(&aggm[(size_t)row_s[e] * H + k], m);
    }
    __syncthreads();

    // GEMM2: cv = silu(m @ c1 + cb)
    #pragma unroll
    for (int e = 0; e < TILE; e++) acc[e] = 0.f;
    for (int j = 0; j < H; j += 4) {
        float w0 = c1[(j + 0) * H + k];
        float w1v = c1[(j + 1) * H + k];
        float w2v = c1[(j + 2) * H + k];
        float w3 = c1[(j + 3) * H + k];
        #pragma unroll
        for (int e = 0; e < TILE; e++) {
            float4 v = *reinterpret_cast<const float4*>(&hid[e][j]);
            acc[e] = fmaf(v.x, w0, acc[e]);
            acc[e] = fmaf(v.y, w1v, acc[e]);
            acc[e] = fmaf(v.z, w2v, acc[e]);
            acc[e] = fmaf(v.w, w3, acc[e]);
        }
    }
    float cbk = cb[k], c2k = c2[k];
    __syncthreads();   // all reads of hid (m) done
    #pragma unroll 4
    for (int e = 0; e < TILE; e++) {
        float cv = silu_f(acc[e] + cbk);
        hid[e][k] = cv * c2k;
    }
    __syncthreads();

    // per-edge reduction of cv*c2 over k, then trans atomics
    int warp = k >> 5, lane = k & 31;
    #pragma unroll
    for (int e = warp * 8; e < warp * 8 + 8; e++) {
        float s = hid[e][lane] + hid[e][lane + 32] + hid[e][lane + 64] + hid[e][lane + 96];
        #pragma unroll
        for (int off = 16; off; off >>= 1) s += __shfl_xor_sync(0xffffffffu, s, off);
        if (lane == 0) {
            float wv = tanhf(s);
            float dist = sqrtf(dsq_s[e] + EPS_F);
            float inv = wv / (dist + EPS_F);
            int r = row_s[e];
            atomicAdd(&aggx[r * 3 + 0], diff_s[e][0] * inv);
            atomicAdd(&aggx[r * 3 + 1], diff_s[e][1] * inv);
            atomicAdd(&aggx[r * 3 + 2], diff_s[e][2] * inv);
        }
    }
}

// ---------------- per-layer node update ----------------
__global__ void node_update_kernel(float* __restrict__ hf, const float* __restrict__ aggm,
                                   float* __restrict__ xb, const float* __restrict__ aggx,
                                   const float* __restrict__ mask,
                                   const float* __restrict__ n1, const float* __restrict__ nb1,
                                   const float* __restrict__ n2, const float* __restrict__ nb2) {
    __shared__ float ins[2 * H];
    __shared__ float hid[H];
    int i = blockIdx.x, k = threadIdx.x;
    float hfk = hf[i * H + k];
    ins[k] = hfk;
    ins[H + k] = aggm[i * H + k];
    __syncthreads();
    float a = nb1[k];
    for (int j = 0; j < 2 * H; j += 4) {
        float4 v = *reinterpret_cast<const float4*>(&ins[j]);
        a = fmaf(v.x, n1[(j + 0) * H + k], a);
        a = fmaf(v.y, n1[(j + 1) * H + k], a);
        a = fmaf(v.z, n1[(j + 2) * H + k], a);
        a = fmaf(v.w, n1[(j + 3) * H + k], a);
    }
    hid[k] = silu_f(a);
    __syncthreads();
    float b = nb2[k];
    for (int j = 0; j < H; j += 4) {
        float4 v = *reinterpret_cast<const float4*>(&hid[j]);
        b = fmaf(v.x, n2[(j + 0) * H + k], b);
        b = fmaf(v.y, n2[(j + 1) * H + k], b);
        b = fmaf(v.z, n2[(j + 2) * H + k], b);
        b = fmaf(v.w, n2[(j + 3) * H + k], b);
    }
    hf[i * H + k] = hfk + b;
    if (k < 3) xb[i * 3 + k] += aggx[i * 3 + k] * mask[i];
}

// ---------------- final velocity ----------------
__global__ void v_kernel(const float* __restrict__ xb, const float* __restrict__ x_in,
                         const float* __restrict__ mask, float* __restrict__ out) {
    int idx = blockIdx.x * blockDim.x + threadIdx.x;
    if (idx < N_NODES * 3) {
        int i = idx / 3;
        out[idx] = (xb[idx] - x_in[idx]) * mask[i];
    }
}

extern "C" void kernel_launch(void* const* d_in, const int* in_sizes, int n_in,
                              void* d_out, int out_size) {
    const float* h        = (const float*)d_in[0];
    const float* x        = (const float*)d_in[1];
    const int*   ei       = (const int*)d_in[2];
    const float* ea       = (const float*)d_in[3];
    const float* t        = (const float*)d_in[4];
    const float* mask     = (const float*)d_in[5];
    const float* tw1      = (const float*)d_in[6];
    const float* tb1      = (const float*)d_in[7];
    const float* tw2      = (const float*)d_in[8];
    const float* tb2      = (const float*)d_in[9];
    const float* new_     = (const float*)d_in[10];
    const float* neb      = (const float*)d_in[11];
    const float* eew      = (const float*)d_in[12];
    const float* eeb      = (const float*)d_in[13];
    const float* ew1      = (const float*)d_in[14];
    const float* eb1      = (const float*)d_in[15];
    const float* ew2      = (const float*)d_in[16];
    const float* eb2      = (const float*)d_in[17];
    const float* cw1      = (const float*)d_in[18];
    const float* cb1      = (const float*)d_in[19];
    const float* cw2      = (const float*)d_in[20];
    const float* nw1      = (const float*)d_in[21];
    const float* nb1      = (const float*)d_in[22];
    const float* nw2      = (const float*)d_in[23];
    const float* nb2      = (const float*)d_in[24];
    float* out = (float*)d_out;

    float *temb, *hfeat, *Ab, *Bb, *xb, *aggm, *aggx, *Mb, *c0b;
    cudaGetSymbolAddress((void**)&temb,  g_temb);
    cudaGetSymbolAddress((void**)&hfeat, g_hfeat);
    cudaGetSymbolAddress((void**)&Ab,    g_A);
    cudaGetSymbolAddress((void**)&Bb,    g_B);
    cudaGetSymbolAddress((void**)&xb,    g_x);
    cudaGetSymbolAddress((void**)&aggm,  g_aggm);
    cudaGetSymbolAddress((void**)&aggx,  g_aggx);
    cudaGetSymbolAddress((void**)&Mb,    g_M);
    cudaGetSymbolAddress((void**)&c0b,   g_c0);

    time_emb_kernel<<<1, H>>>(t, tw1, tb1, tw2, tb2, temb);
    node_embed_kernel<<<N_NODES, H>>>(h, new_, neb, temb, x, hfeat, xb);

    for (int l = 0; l < L_LAYERS; l++) {
        const float* w1  = ew1 + (size_t)l * 385 * H;
        const float* b1  = eb1 + l * H;
        const float* w2  = ew2 + (size_t)l * H * H;
        const float* b2  = eb2 + l * H;
        const float* c1  = cw1 + (size_t)l * H * H;
        const float* cb  = cb1 + l * H;
        const float* c2  = cw2 + l * H;
        const float* n1  = nw1 + (size_t)l * 2 * H * H;
        const float* nb1l = nb1 + l * H;
        const float* n2  = nw2 + (size_t)l * H * H;
        const float* nb2l = nb2 + l * H;

        prep_kernel<<<1, H>>>(eew, eeb, w1 + 257 * H, b1, Mb, c0b);
        ab_kernel<<<N_NODES, H>>>(hfeat, w1, Ab, Bb, aggm, aggx);
        edge_kernel<<<N_EDGES / TILE, H>>>(ei, ei + N_EDGES, xb, Ab, Bb, ea,
                                           Mb, c0b, w1 + 256 * H, w2, b2, c1, cb, c2,
                                           aggm, aggx);
        node_update_kernel<<<N_NODES, H>>>(hfeat, aggm, xb, aggx, mask,
                                           n1, nb1l, n2, nb2l);
    }
    v_kernel<<<(N_NODES * 3 + 127) / 128, 128>>>(xb, x, mask, out);
}

// round 5
// speedup vs baseline: 1.4315x; 1.0242x over previous
#include <cuda_runtime.h>
#include <cuda_bf16.h>
#include <math.h>
#include <stdint.h>

#define N_NODES 10000
#define N_EDGES 320000
#define H 128
#define NODE_IN 64
#define EDGE_IN 16
#define L_LAYERS 4
#define EPS_F 1e-8f
#define TILE_E 128
#define NB 8

// ---------------- scratch (device globals; no allocation allowed) ----------------
__device__ float g_temb[H];
__device__ float g_hfeat[N_NODES * H];
__device__ float g_A[N_NODES * H];
__device__ float g_B[N_NODES * H];
__device__ float g_x[N_NODES * 3];
__device__ float g_aggm[N_NODES * H];
__device__ float g_aggx[N_NODES * 3];
__device__ float g_M[EDGE_IN * H];   // folded low-rank edge weight
__device__ float g_c0[H];            // folded bias
// bf16 hi/lo weight images, plain row-major [k][n] 128x128 (32KB each)
__device__ __align__(16) unsigned char g_w2hi[32768];
__device__ __align__(16) unsigned char g_w2lo[32768];
__device__ __align__(16) unsigned char g_c1hi[32768];
__device__ __align__(16) unsigned char g_c1lo[32768];

__device__ __forceinline__ float silu_f(float v) {
    return v / (1.0f + __expf(-v));
}

__device__ __forceinline__ uint32_t smem_u32(const void* p) {
    uint32_t a;
    asm("{ .reg .u64 t; cvta.to.shared.u64 t, %1; cvt.u32.u64 %0, t; }" : "=r"(a) : "l"(p));
    return a;
}

__device__ __forceinline__ void ldsm_x4(uint32_t* r, uint32_t addr) {
    asm volatile("ldmatrix.sync.aligned.m8n8.x4.shared.b16 {%0,%1,%2,%3}, [%4];"
        : "=r"(r[0]), "=r"(r[1]), "=r"(r[2]), "=r"(r[3]) : "r"(addr));
}
__device__ __forceinline__ void ldsm_x2t(uint32_t* r, uint32_t addr) {
    asm volatile("ldmatrix.sync.aligned.m8n8.x2.trans.shared.b16 {%0,%1}, [%2];"
        : "=r"(r[0]), "=r"(r[1]) : "r"(addr));
}
__device__ __forceinline__ void mma16816(float* d, const uint32_t* a, const uint32_t* b) {
    asm volatile("mma.sync.aligned.m16n8k16.row.col.f32.bf16.bf16.f32 "
        "{%0,%1,%2,%3}, {%4,%5,%6,%7}, {%8,%9}, {%0,%1,%2,%3};"
        : "+f"(d[0]), "+f"(d[1]), "+f"(d[2]), "+f"(d[3])
        : "r"(a[0]), "r"(a[1]), "r"(a[2]), "r"(a[3]), "r"(b[0]), "r"(b[1]));
}

__device__ __forceinline__ uint32_t pack2bf16(float a, float b) {
    uint32_t ua = (uint32_t)__bfloat16_as_ushort(__float2bfloat16(a));
    uint32_t ub = (uint32_t)__bfloat16_as_ushort(__float2bfloat16(b));
    return ua | (ub << 16);
}

// ---------------- t embedding ----------------
__global__ void time_emb_kernel(const float* __restrict__ t,
                                const float* __restrict__ w1, const float* __restrict__ b1,
                                const float* __restrict__ w2, const float* __restrict__ b2,
                                float* __restrict__ temb) {
    __shared__ float h1[H];
    int k = threadIdx.x;
    h1[k] = silu_f(t[0] * w1[k] + b1[k]);
    __syncthreads();
    float acc = b2[k];
    #pragma unroll 4
    for (int j = 0; j < H; j++) acc = fmaf(h1[j], w2[j * H + k], acc);
    temb[k] = acc;
}

// ---------------- node embedding + x init ----------------
__global__ void node_embed_kernel(const float* __restrict__ h,
                                  const float* __restrict__ W, const float* __restrict__ b,
                                  const float* __restrict__ temb,
                                  const float* __restrict__ x_in,
                                  float* __restrict__ hf, float* __restrict__ xb) {
    __shared__ float hs[NODE_IN];
    int i = blockIdx.x, k = threadIdx.x;
    if (k < NODE_IN) hs[k] = h[i * NODE_IN + k];
    __syncthreads();
    float acc = b[k] + temb[k];
    #pragma unroll
    for (int j = 0; j < NODE_IN; j += 4) {
        float4 v = *reinterpret_cast<const float4*>(&hs[j]);
        acc = fmaf(v.x, W[(j + 0) * H + k], acc);
        acc = fmaf(v.y, W[(j + 1) * H + k], acc);
        acc = fmaf(v.z, W[(j + 2) * H + k], acc);
        acc = fmaf(v.w, W[(j + 3) * H + k], acc);
    }
    hf[i * H + k] = acc;
    if (k < 3) xb[i * 3 + k] = x_in[i * 3 + k];
}

// ---------------- per-layer: fold M = Wee @ W1c (16x128), c0 = beb@W1c + b1 ----------------
__global__ void prep_kernel(const float* __restrict__ eew, const float* __restrict__ eeb,
                            const float* __restrict__ w1c, const float* __restrict__ b1,
                            float* __restrict__ M, float* __restrict__ c0) {
    __shared__ float es[EDGE_IN][H];
    __shared__ float ebs[H];
    int k = threadIdx.x;
    #pragma unroll
    for (int i = 0; i < EDGE_IN; i++) es[i][k] = eew[i * H + k];
    ebs[k] = eeb[k];
    __syncthreads();
    float m[EDGE_IN];
    #pragma unroll
    for (int i = 0; i < EDGE_IN; i++) m[i] = 0.f;
    float c = b1[k];
    for (int j = 0; j < H; j++) {
        float w = w1c[j * H + k];
        c = fmaf(ebs[j], w, c);
        #pragma unroll
        for (int i = 0; i < EDGE_IN; i++) m[i] = fmaf(es[i][j], w, m[i]);
    }
    #pragma unroll
    for (int i = 0; i < EDGE_IN; i++) M[i * H + k] = m[i];
    c0[k] = c;
}

// ---------------- per-layer: convert w2/c1 -> bf16 hi/lo images [k][n] ----------------
__global__ void prep_w_kernel(const float* __restrict__ w2, const float* __restrict__ c1) {
    int kk = blockIdx.x & 127;
    int n = threadIdx.x;
    const float* W = (blockIdx.x < 128) ? w2 : c1;
    __nv_bfloat16* hi_img = (__nv_bfloat16*)((blockIdx.x < 128) ? g_w2hi : g_c1hi);
    __nv_bfloat16* lo_img = (__nv_bfloat16*)((blockIdx.x < 128) ? g_w2lo : g_c1lo);
    float v = W[kk * H + n];
    __nv_bfloat16 hv = __float2bfloat16(v);
    __nv_bfloat16 lv = __float2bfloat16(v - __bfloat162float(hv));
    hi_img[kk * H + n] = hv;
    lo_img[kk * H + n] = lv;
}

// ---------------- per-layer: A/B projections, NB nodes per block; zero agg ----------------
__global__ void __launch_bounds__(128) ab_kernel(
    const float* __restrict__ hf, const float* __restrict__ w1,
    float* __restrict__ A, float* __restrict__ B,
    float* __restrict__ aggm, float* __restrict__ aggx) {
    __shared__ float hs[NB][H];
    int i0 = blockIdx.x * NB, k = threadIdx.x;
    #pragma unroll
    for (int n = 0; n < NB; n++) {
        hs[n][k] = hf[(size_t)(i0 + n) * H + k];
        aggm[(size_t)(i0 + n) * H + k] = 0.f;
    }
    if (k < 3 * NB) aggx[i0 * 3 + k] = 0.f;
    __syncthreads();
    float a[NB], b[NB];
    #pragma unroll
    for (int n = 0; n < NB; n++) { a[n] = 0.f; b[n] = 0.f; }
    for (int j = 0; j < H; j += 4) {
        float wa0 = w1[(j + 0) * H + k], wa1 = w1[(j + 1) * H + k];
        float wa2 = w1[(j + 2) * H + k], wa3 = w1[(j + 3) * H + k];
        float wb0 = w1[(H + j + 0) * H + k], wb1 = w1[(H + j + 1) * H + k];
        float wb2 = w1[(H + j + 2) * H + k], wb3 = w1[(H + j + 3) * H + k];
        #pragma unroll
        for (int n = 0; n < NB; n++) {
            float4 v = *reinterpret_cast<const float4*>(&hs[n][j]);
            a[n] = fmaf(v.x, wa0, a[n]); a[n] = fmaf(v.y, wa1, a[n]);
            a[n] = fmaf(v.z, wa2, a[n]); a[n] = fmaf(v.w, wa3, a[n]);
            b[n] = fmaf(v.x, wb0, b[n]); b[n] = fmaf(v.y, wb1, b[n]);
            b[n] = fmaf(v.z, wb2, b[n]); b[n] = fmaf(v.w, wb3, b[n]);
        }
    }
    #pragma unroll
    for (int n = 0; n < NB; n++) {
        A[(size_t)(i0 + n) * H + k] = a[n];
        B[(size_t)(i0 + n) * H + k] = b[n];
    }
}

// ---------------- edge kernel: warp-MMA version ----------------
// smem layout (bytes). A/W tiles: 128 rows x 272B (136 bf16, conflict-free ldmatrix)
#define SM_AHI   0
#define SM_ALO   34816
#define SM_WHI   69632
#define SM_WLO   104448
#define SM_EAS   139264
#define SM_MS    147456
#define SM_B2    155648
#define SM_CB    156160
#define SM_C2    156672
#define SM_C0    157184
#define SM_W1D   157696
#define SM_DIFF  158208
#define SM_DSQ   159744
#define SM_ROW   160256
#define SM_COL   160768
#define SM_SPART 161280
#define SMEM_EDGE_TOTAL 161792

#define ASTRIDE 272   // bytes per row (136 bf16)

extern "C" __global__ void __launch_bounds__(256, 1) edge_kernel(
    const int* __restrict__ row, const int* __restrict__ col,
    const float* __restrict__ x,
    const float* __restrict__ Ag, const float* __restrict__ Bg,
    const float* __restrict__ ea,
    const float* __restrict__ Mg, const float* __restrict__ c0g,
    const float* __restrict__ w1d,
    const float* __restrict__ b2, const float* __restrict__ cb,
    const float* __restrict__ c2,
    float* __restrict__ aggm, float* __restrict__ aggx) {
    extern __shared__ unsigned char smem[];
    const uint32_t smem_base = smem_u32(smem);
    int tid = threadIdx.x;
    int wid = tid >> 5, lane = tid & 31;
    int g = lane >> 2, tig = lane & 3;
    int k = tid & 127, eh = tid >> 7;
    int e0 = blockIdx.x * TILE_E;

    float* Ms    = (float*)(smem + SM_MS);
    float* EAs   = (float*)(smem + SM_EAS);
    float* B2s   = (float*)(smem + SM_B2);
    float* CBs   = (float*)(smem + SM_CB);
    float* C2s   = (float*)(smem + SM_C2);
    float* C0s   = (float*)(smem + SM_C0);
    float* W1Ds  = (float*)(smem + SM_W1D);
    float* DIFFs = (float*)(smem + SM_DIFF);
    float* DSQs  = (float*)(smem + SM_DSQ);
    int*   ROWs  = (int*)(smem + SM_ROW);
    int*   COLs  = (int*)(smem + SM_COL);
    float* SPARTs= (float*)(smem + SM_SPART);
    __nv_bfloat16* AHIb = (__nv_bfloat16*)(smem + SM_AHI);
    __nv_bfloat16* ALOb = (__nv_bfloat16*)(smem + SM_ALO);

    // stage w2 hi/lo images into smem (row-major, 272B stride)
    {
        const uint4* shi = (const uint4*)g_w2hi;
        const uint4* slo = (const uint4*)g_w2lo;
        for (int i = tid; i < 2048; i += 256) {
            int r = i >> 4, c = i & 15;
            *(uint4*)(smem + SM_WHI + r * ASTRIDE + c * 16) = shi[i];
            *(uint4*)(smem + SM_WLO + r * ASTRIDE + c * 16) = slo[i];
        }
    }
    for (int i = tid; i < EDGE_IN * H; i += 256) Ms[i] = Mg[i];
    {
        const float4* src = (const float4*)(ea + (size_t)e0 * EDGE_IN);
        float4* dst = (float4*)EAs;
        for (int i = tid; i < TILE_E * EDGE_IN / 4; i += 256) dst[i] = src[i];
    }
    if (tid < H) {
        B2s[tid] = b2[tid]; CBs[tid] = cb[tid]; C2s[tid] = c2[tid];
        C0s[tid] = c0g[tid]; W1Ds[tid] = w1d[tid];
    }
    if (tid < TILE_E) {
        int e = e0 + tid;
        int r = row[e], c = col[e];
        ROWs[tid] = r; COLs[tid] = c;
        float dx = x[r * 3 + 0] - x[c * 3 + 0];
        float dy = x[r * 3 + 1] - x[c * 3 + 1];
        float dz = x[r * 3 + 2] - x[c * 3 + 2];
        DIFFs[tid * 3 + 0] = dx; DIFFs[tid * 3 + 1] = dy; DIFFs[tid * 3 + 2] = dz;
        DSQs[tid] = dx * dx + dy * dy + dz * dz;
    }
    __syncthreads();

    // build hidden tile: silu(A[r] + B[c] + c0 + dsq*w1d + ea@M), split bf16 hi/lo
    {
        float c0k = C0s[k], w1dk = W1Ds[k];
        #pragma unroll 2
        for (int e = eh; e < TILE_E; e += 2) {
            int r = ROWs[e], c = COLs[e];
            float pre = Ag[(size_t)r * H + k] + Bg[(size_t)c * H + k]
                      + c0k + DSQs[e] * w1dk;
            const float4* eav = (const float4*)&EAs[e * EDGE_IN];
            float4 v0 = eav[0], v1 = eav[1], v2 = eav[2], v3 = eav[3];
            pre = fmaf(v0.x, Ms[0 * H + k], pre);  pre = fmaf(v0.y, Ms[1 * H + k], pre);
            pre = fmaf(v0.z, Ms[2 * H + k], pre);  pre = fmaf(v0.w, Ms[3 * H + k], pre);
            pre = fmaf(v1.x, Ms[4 * H + k], pre);  pre = fmaf(v1.y, Ms[5 * H + k], pre);
            pre = fmaf(v1.z, Ms[6 * H + k], pre);  pre = fmaf(v1.w, Ms[7 * H + k], pre);
            pre = fmaf(v2.x, Ms[8 * H + k], pre);  pre = fmaf(v2.y, Ms[9 * H + k], pre);
            pre = fmaf(v2.z, Ms[10 * H + k], pre); pre = fmaf(v2.w, Ms[11 * H + k], pre);
            pre = fmaf(v3.x, Ms[12 * H + k], pre); pre = fmaf(v3.y, Ms[13 * H + k], pre);
            pre = fmaf(v3.z, Ms[14 * H + k], pre); pre = fmaf(v3.w, Ms[15 * H + k], pre);
            float hv = silu_f(pre);
            __nv_bfloat16 hh = __float2bfloat16(hv);
            __nv_bfloat16 hl = __float2bfloat16(hv - __bfloat162float(hh));
            AHIb[e * 136 + k] = hh;
            ALOb[e * 136 + k] = hl;
        }
    }
    __syncthreads();

    // ldmatrix base offsets
    uint32_t aRowOff = (uint32_t)((16 * wid + (lane & 15)) * ASTRIDE + (lane >> 4) * 16);
    uint32_t bRowLane = (uint32_t)((lane & 15) * ASTRIDE);

    float d[16][4];

    // ---------------- GEMM1: D = hidden @ w2 ----------------
    #pragma unroll
    for (int nt = 0; nt < 16; nt++) { d[nt][0] = d[nt][1] = d[nt][2] = d[nt][3] = 0.f; }
    for (int kt = 0; kt < 8; kt++) {
        uint32_t ahi[4], alo[4];
        ldsm_x4(ahi, smem_base + SM_AHI + aRowOff + kt * 32);
        ldsm_x4(alo, smem_base + SM_ALO + aRowOff + kt * 32);
        uint32_t bBase = (uint32_t)(kt * 16 * ASTRIDE) + bRowLane;
        #pragma unroll
        for (int nt = 0; nt < 16; nt++) {
            uint32_t bhi[2], blo[2];
            ldsm_x2t(bhi, smem_base + SM_WHI + bBase + nt * 16);
            ldsm_x2t(blo, smem_base + SM_WLO + bBase + nt * 16);
            mma16816(d[nt], ahi, bhi);
            mma16816(d[nt], alo, bhi);
            mma16816(d[nt], ahi, blo);
        }
    }

    // epilogue1: m = silu(D + b2) -> overwrite A tiles (hi/lo), own rows only
    {
        int e_lo = 16 * wid + g, e_hi = e_lo + 8;
        #pragma unroll
        for (int nt = 0; nt < 16; nt++) {
            int ch0 = nt * 8 + 2 * tig;
            float m00 = silu_f(d[nt][0] + B2s[ch0]);
            float m01 = silu_f(d[nt][1] + B2s[ch0 + 1]);
            float m10 = silu_f(d[nt][2] + B2s[ch0]);
            float m11 = silu_f(d[nt][3] + B2s[ch0 + 1]);
            float h00 = __bfloat162float(__float2bfloat16(m00));
            float h01 = __bfloat162float(__float2bfloat16(m01));
            float h10 = __bfloat162float(__float2bfloat16(m10));
            float h11 = __bfloat162float(__float2bfloat16(m11));
            *(uint32_t*)(smem + SM_AHI + e_lo * ASTRIDE + ch0 * 2) = pack2bf16(h00, h01);
            *(uint32_t*)(smem + SM_AHI + e_hi * ASTRIDE + ch0 * 2) = pack2bf16(h10, h11);
            *(uint32_t*)(smem + SM_ALO + e_lo * ASTRIDE + ch0 * 2) = pack2bf16(m00 - h00, m01 - h01);
            *(uint32_t*)(smem + SM_ALO + e_hi * ASTRIDE + ch0 * 2) = pack2bf16(m10 - h10, m11 - h11);
        }
    }
    __syncthreads();

    // stage c1 images (overwrite W buffers) + aggm atomics from smem m
    {
        const uint4* shi = (const uint4*)g_c1hi;
        const uint4* slo = (const uint4*)g_c1lo;
        for (int i = tid; i < 2048; i += 256) {
            int r = i >> 4, c = i & 15;
            *(uint4*)(smem + SM_WHI + r * ASTRIDE + c * 16) = shi[i];
            *(uint4*)(smem + SM_WLO + r * ASTRIDE + c * 16) = slo[i];
        }
    }
    for (int t = 0; t < 16; t++) {
        int e2 = wid * 16 + t;
        float* dst = aggm + (size_t)ROWs[e2] * H;
        #pragma unroll
        for (int i2 = 0; i2 < 4; i2++) {
            int ch = lane + 32 * i2;
            float hv = __bfloat162float(AHIb[e2 * 136 + ch]);
            float lv = __bfloat162float(ALOb[e2 * 136 + ch]);
            atomicAdd(dst + ch, hv + lv);
        }
    }
    __syncthreads();

    // ---------------- GEMM2: D = m @ c1 ----------------
    #pragma unroll
    for (int nt = 0; nt < 16; nt++) { d[nt][0] = d[nt][1] = d[nt][2] = d[nt][3] = 0.f; }
    for (int kt = 0; kt < 8; kt++) {
        uint32_t ahi[4], alo[4];
        ldsm_x4(ahi, smem_base + SM_AHI + aRowOff + kt * 32);
        ldsm_x4(alo, smem_base + SM_ALO + aRowOff + kt * 32);
        uint32_t bBase = (uint32_t)(kt * 16 * ASTRIDE) + bRowLane;
        #pragma unroll
        for (int nt = 0; nt < 16; nt++) {
            uint32_t bhi[2], blo[2];
            ldsm_x2t(bhi, smem_base + SM_WHI + bBase + nt * 16);
            ldsm_x2t(blo, smem_base + SM_WLO + bBase + nt * 16);
            mma16816(d[nt], ahi, bhi);
            mma16816(d[nt], alo, bhi);
            mma16816(d[nt], ahi, blo);
        }
    }

    // epilogue2: per-edge s = sum_ch silu(D + cb) * c2
    {
        float sLow = 0.f, sHigh = 0.f;
        #pragma unroll
        for (int nt = 0; nt < 16; nt++) {
            int ch0 = nt * 8 + 2 * tig;
            float cb0 = CBs[ch0], cb1 = CBs[ch0 + 1];
            float cc0 = C2s[ch0], cc1 = C2s[ch0 + 1];
            sLow  = fmaf(silu_f(d[nt][0] + cb0), cc0, sLow);
            sLow  = fmaf(silu_f(d[nt][1] + cb1), cc1, sLow);
            sHigh = fmaf(silu_f(d[nt][2] + cb0), cc0, sHigh);
            sHigh = fmaf(silu_f(d[nt][3] + cb1), cc1, sHigh);
        }
        sLow += __shfl_xor_sync(0xffffffffu, sLow, 1);
        sLow += __shfl_xor_sync(0xffffffffu, sLow, 2);
        sHigh += __shfl_xor_sync(0xffffffffu, sHigh, 1);
        sHigh += __shfl_xor_sync(0xffffffffu, sHigh, 2);
        if (tig == 0) {
            SPARTs[16 * wid + g] = sLow;
            SPARTs[16 * wid + 8 + g] = sHigh;
        }
    }
    __syncthreads();

    if (tid < TILE_E) {
        float wv = tanhf(SPARTs[tid]);
        float dist = sqrtf(DSQs[tid] + EPS_F);
        float inv = wv / (dist + EPS_F);
        int r = ROWs[tid];
        atomicAdd(&aggx[r * 3 + 0], DIFFs[tid * 3 + 0] * inv);
        atomicAdd(&aggx[r * 3 + 1], DIFFs[tid * 3 + 1] * inv);
        atomicAdd(&aggx[r * 3 + 2], DIFFs[tid * 3 + 2] * inv);
    }
}

// ---------------- per-layer node update, NB nodes per block ----------------
__global__ void __launch_bounds__(128) node_update_kernel(
    float* __restrict__ hf, const float* __restrict__ aggm,
    float* __restrict__ xb, const float* __restrict__ aggx,
    const float* __restrict__ mask,
    const float* __restrict__ n1, const float* __restrict__ nb1,
    const float* __restrict__ n2, const float* __restrict__ nb2) {
    __shared__ float ins[NB][2 * H];
    __shared__ float hid[NB][H];
    int i0 = blockIdx.x * NB, k = threadIdx.x;
    #pragma unroll
    for (int n = 0; n < NB; n++) {
        ins[n][k] = hf[(size_t)(i0 + n) * H + k];
        ins[n][H + k] = aggm[(size_t)(i0 + n) * H + k];
    }
    __syncthreads();
    float a[NB];
    {
        float nb = nb1[k];
        #pragma unroll
        for (int n = 0; n < NB; n++) a[n] = nb;
    }
    for (int j = 0; j < 2 * H; j += 4) {
        float w0 = n1[(j + 0) * H + k], w1v = n1[(j + 1) * H + k];
        float w2v = n1[(j + 2) * H + k], w3 = n1[(j + 3) * H + k];
        #pragma unroll
        for (int n = 0; n < NB; n++) {
            float4 v = *reinterpret_cast<const float4*>(&ins[n][j]);
            a[n] = fmaf(v.x, w0, a[n]); a[n] = fmaf(v.y, w1v, a[n]);
            a[n] = fmaf(v.z, w2v, a[n]); a[n] = fmaf(v.w, w3, a[n]);
        }
    }
    #pragma unroll
    for (int n = 0; n < NB; n++) hid[n][k] = silu_f(a[n]);
    __syncthreads();
    float b[NB];
    {
        float nb = nb2[k];
        #pragma unroll
        for (int n = 0; n < NB; n++) b[n] = nb;
    }
    for (int j = 0; j < H; j += 4) {
        float w0 = n2[(j + 0) * H + k], w1v = n2[(j + 1) * H + k];
        float w2v = n2[(j + 2) * H + k], w3 = n2[(j + 3) * H + k];
        #pragma unroll
        for (int n = 0; n < NB; n++) {
            float4 v = *reinterpret_cast<const float4*>(&hid[n][j]);
            b[n] = fmaf(v.x, w0, b[n]); b[n] = fmaf(v.y, w1v, b[n]);
            b[n] = fmaf(v.z, w2v, b[n]); b[n] = fmaf(v.w, w3, b[n]);
        }
    }
    #pragma unroll
    for (int n = 0; n < NB; n++)
        hf[(size_t)(i0 + n) * H + k] = ins[n][k] + b[n];
    if (k < 3 * NB) {
        int n = k / 3;
        xb[i0 * 3 + k] += aggx[i0 * 3 + k] * mask[i0 + n];
    }
}

// ---------------- final velocity ----------------
__global__ void v_kernel(const float* __restrict__ xb, const float* __restrict__ x_in,
                         const float* __restrict__ mask, float* __restrict__ out) {
    int idx = blockIdx.x * blockDim.x + threadIdx.x;
    if (idx < N_NODES * 3) {
        int i = idx / 3;
        out[idx] = (xb[idx] - x_in[idx]) * mask[i];
    }
}

extern "C" void kernel_launch(void* const* d_in, const int* in_sizes, int n_in,
                              void* d_out, int out_size) {
    const float* h        = (const float*)d_in[0];
    const float* x        = (const float*)d_in[1];
    const int*   ei       = (const int*)d_in[2];
    const float* ea       = (const float*)d_in[3];
    const float* t        = (const float*)d_in[4];
    const float* mask     = (const float*)d_in[5];
    const float* tw1      = (const float*)d_in[6];
    const float* tb1      = (const float*)d_in[7];
    const float* tw2      = (const float*)d_in[8];
    const float* tb2      = (const float*)d_in[9];
    const float* new_     = (const float*)d_in[10];
    const float* neb      = (const float*)d_in[11];
    const float* eew      = (const float*)d_in[12];
    const float* eeb      = (const float*)d_in[13];
    const float* ew1      = (const float*)d_in[14];
    const float* eb1      = (const float*)d_in[15];
    const float* ew2      = (const float*)d_in[16];
    const float* eb2      = (const float*)d_in[17];
    const float* cw1      = (const float*)d_in[18];
    const float* cb1      = (const float*)d_in[19];
    const float* cw2      = (const float*)d_in[20];
    const float* nw1      = (const float*)d_in[21];
    const float* nb1      = (const float*)d_in[22];
    const float* nw2      = (const float*)d_in[23];
    const float* nb2      = (const float*)d_in[24];
    float* out = (float*)d_out;

    float *temb, *hfeat, *Ab, *Bb, *xb, *aggm, *aggx, *Mb, *c0b;
    cudaGetSymbolAddress((void**)&temb,  g_temb);
    cudaGetSymbolAddress((void**)&hfeat, g_hfeat);
    cudaGetSymbolAddress((void**)&Ab,    g_A);
    cudaGetSymbolAddress((void**)&Bb,    g_B);
    cudaGetSymbolAddress((void**)&xb,    g_x);
    cudaGetSymbolAddress((void**)&aggm,  g_aggm);
    cudaGetSymbolAddress((void**)&aggx,  g_aggx);
    cudaGetSymbolAddress((void**)&Mb,    g_M);
    cudaGetSymbolAddress((void**)&c0b,   g_c0);

    cudaFuncSetAttribute(edge_kernel, cudaFuncAttributeMaxDynamicSharedMemorySize,
                         SMEM_EDGE_TOTAL);

    time_emb_kernel<<<1, H>>>(t, tw1, tb1, tw2, tb2, temb);
    node_embed_kernel<<<N_NODES, H>>>(h, new_, neb, temb, x, hfeat, xb);

    for (int l = 0; l < L_LAYERS; l++) {
        const float* w1  = ew1 + (size_t)l * 385 * H;
        const float* b1  = eb1 + l * H;
        const float* w2  = ew2 + (size_t)l * H * H;
        const float* b2  = eb2 + l * H;
        const float* c1  = cw1 + (size_t)l * H * H;
        const float* cb  = cb1 + l * H;
        const float* c2  = cw2 + l * H;
        const float* n1  = nw1 + (size_t)l * 2 * H * H;
        const float* nb1l = nb1 + l * H;
        const float* n2  = nw2 + (size_t)l * H * H;
        const float* nb2l = nb2 + l * H;

        prep_kernel<<<1, H>>>(eew, eeb, w1 + 257 * H, b1, Mb, c0b);
        prep_w_kernel<<<256, H>>>(w2, c1);
        ab_kernel<<<N_NODES / NB, H>>>(hfeat, w1, Ab, Bb, aggm, aggx);
        edge_kernel<<<N_EDGES / TILE_E, 256, SMEM_EDGE_TOTAL>>>(
            ei, ei + N_EDGES, xb, Ab, Bb, ea, Mb, c0b, w1 + 256 * H,
            b2, cb, c2, aggm, aggx);
        node_update_kernel<<<N_NODES / NB, H>>>(hfeat, aggm, xb, aggx, mask,
                                                n1, nb1l, n2, nb2l);
    }
    v_kernel<<<(N_NODES * 3 + 127) / 128, 128>>>(xb, x, mask, out);
}

// round 6
// speedup vs baseline: 1.5046x; 1.0511x over previous
#include <cuda_runtime.h>
#include <cuda_bf16.h>
#include <math.h>
#include <stdint.h>

#define N_NODES 10000
#define N_EDGES 320000
#define H 128
#define NODE_IN 64
#define EDGE_IN 16
#define L_LAYERS 4
#define EPS_F 1e-8f
#define TILE_E 128
#define NB 8

// ---------------- scratch (device globals; no allocation allowed) ----------------
__device__ float g_temb[H];
__device__ float g_hfeat[N_NODES * H];
__device__ float g_A[N_NODES * H];
__device__ float g_B[N_NODES * H];
__device__ float g_x[N_NODES * 3];
__device__ float g_aggm[N_NODES * H];
__device__ float g_aggx[N_NODES * 3];
__device__ float g_M[L_LAYERS * EDGE_IN * H];   // folded low-rank edge weights (all layers)
__device__ float g_c0[L_LAYERS * H];            // folded biases (all layers)
// B fragments in MMA order: [layer][kt(8)][nt(16)][lane(32)] -> uint4 {bhi0,bhi1,blo0,blo1}
__device__ uint4 g_w2f[L_LAYERS * 4096];
__device__ uint4 g_c1f[L_LAYERS * 4096];

__device__ __forceinline__ float silu_f(float v) {
    return v / (1.0f + __expf(-v));
}

__device__ __forceinline__ uint32_t smem_u32(const void* p) {
    uint32_t a;
    asm("{ .reg .u64 t; cvta.to.shared.u64 t, %1; cvt.u32.u64 %0, t; }" : "=r"(a) : "l"(p));
    return a;
}

__device__ __forceinline__ void ldsm_x4(uint32_t* r, uint32_t addr) {
    asm volatile("ldmatrix.sync.aligned.m8n8.x4.shared.b16 {%0,%1,%2,%3}, [%4];"
        : "=r"(r[0]), "=r"(r[1]), "=r"(r[2]), "=r"(r[3]) : "r"(addr));
}
__device__ __forceinline__ void mma16816(float* d, const uint32_t* a, uint32_t b0, uint32_t b1) {
    asm volatile("mma.sync.aligned.m16n8k16.row.col.f32.bf16.bf16.f32 "
        "{%0,%1,%2,%3}, {%4,%5,%6,%7}, {%8,%9}, {%0,%1,%2,%3};"
        : "+f"(d[0]), "+f"(d[1]), "+f"(d[2]), "+f"(d[3])
        : "r"(a[0]), "r"(a[1]), "r"(a[2]), "r"(a[3]), "r"(b0), "r"(b1));
}

__device__ __forceinline__ uint32_t pack2bf16(float a, float b) {
    uint32_t ua = (uint32_t)__bfloat16_as_ushort(__float2bfloat16(a));
    uint32_t ub = (uint32_t)__bfloat16_as_ushort(__float2bfloat16(b));
    return ua | (ub << 16);
}

// ---------------- t embedding ----------------
__global__ void time_emb_kernel(const float* __restrict__ t,
                                const float* __restrict__ w1, const float* __restrict__ b1,
                                const float* __restrict__ w2, const float* __restrict__ b2,
                                float* __restrict__ temb) {
    __shared__ float h1[H];
    int k = threadIdx.x;
    h1[k] = silu_f(t[0] * w1[k] + b1[k]);
    __syncthreads();
    float acc = b2[k];
    #pragma unroll 4
    for (int j = 0; j < H; j++) acc = fmaf(h1[j], w2[j * H + k], acc);
    temb[k] = acc;
}

// ---------------- node embedding + x init ----------------
__global__ void node_embed_kernel(const float* __restrict__ h,
                                  const float* __restrict__ W, const float* __restrict__ b,
                                  const float* __restrict__ temb,
                                  const float* __restrict__ x_in,
                                  float* __restrict__ hf, float* __restrict__ xb) {
    __shared__ float hs[NODE_IN];
    int i = blockIdx.x, k = threadIdx.x;
    if (k < NODE_IN) hs[k] = h[i * NODE_IN + k];
    __syncthreads();
    float acc = b[k] + temb[k];
    #pragma unroll
    for (int j = 0; j < NODE_IN; j += 4) {
        float4 v = *reinterpret_cast<const float4*>(&hs[j]);
        acc = fmaf(v.x, W[(j + 0) * H + k], acc);
        acc = fmaf(v.y, W[(j + 1) * H + k], acc);
        acc = fmaf(v.z, W[(j + 2) * H + k], acc);
        acc = fmaf(v.w, W[(j + 3) * H + k], acc);
    }
    hf[i * H + k] = acc;
    if (k < 3) xb[i * 3 + k] = x_in[i * 3 + k];
}

// ---------------- fold M_l = Wee @ W1c_l, c0_l = beb@W1c_l + b1_l (all layers) ----------------
__global__ void prep_kernel(const float* __restrict__ eew, const float* __restrict__ eeb,
                            const float* __restrict__ ew1, const float* __restrict__ eb1,
                            float* __restrict__ M, float* __restrict__ c0) {
    __shared__ float es[EDGE_IN][H];
    __shared__ float ebs[H];
    int l = blockIdx.x;
    const float* w1c = ew1 + (size_t)l * 385 * H + 257 * H;
    const float* b1 = eb1 + l * H;
    int k = threadIdx.x;
    #pragma unroll
    for (int i = 0; i < EDGE_IN; i++) es[i][k] = eew[i * H + k];
    ebs[k] = eeb[k];
    __syncthreads();
    float m[EDGE_IN];
    #pragma unroll
    for (int i = 0; i < EDGE_IN; i++) m[i] = 0.f;
    float c = b1[k];
    for (int j = 0; j < H; j++) {
        float w = w1c[j * H + k];
        c = fmaf(ebs[j], w, c);
        #pragma unroll
        for (int i = 0; i < EDGE_IN; i++) m[i] = fmaf(es[i][j], w, m[i]);
    }
    #pragma unroll
    for (int i = 0; i < EDGE_IN; i++) M[l * EDGE_IN * H + i * H + k] = m[i];
    c0[l * H + k] = c;
}

// ---------------- convert w2/c1 (all layers) -> bf16 hi/lo MMA B-fragments ----------------
// frag index within matrix: kt*512 + nt*32 + lane; value covers B[k][n] with
// n = nt*8 + lane/4, k0 = kt*16 + 2*(lane%4): {hi(k0),hi(k0+1)},{hi(k0+8),hi(k0+9)},
// {lo(k0),lo(k0+1)},{lo(k0+8),lo(k0+9)}
__global__ void prep_w_kernel(const float* __restrict__ ew2, const float* __restrict__ cw1) {
    // grid: 2*L_LAYERS*32 blocks of 128 threads
    int mat = blockIdx.x >> 7;          // 0..? : blockIdx.x / (32*4): 0=w2, 1=c1
    int l = (blockIdx.x >> 5) & 3;      // layer
    int idx = (blockIdx.x & 31) * 128 + threadIdx.x;   // 0..4095
    const float* W = (mat == 0) ? (ew2 + (size_t)l * H * H) : (cw1 + (size_t)l * H * H);
    uint4* out = ((mat == 0) ? g_w2f : g_c1f) + l * 4096;
    int kt = idx >> 9;
    int nt = (idx >> 5) & 15;
    int lane = idx & 31;
    int n = nt * 8 + (lane >> 2);
    int k0 = kt * 16 + 2 * (lane & 3);
    float v00 = W[(k0 + 0) * H + n], v01 = W[(k0 + 1) * H + n];
    float v10 = W[(k0 + 8) * H + n], v11 = W[(k0 + 9) * H + n];
    float h00 = __bfloat162float(__float2bfloat16(v00));
    float h01 = __bfloat162float(__float2bfloat16(v01));
    float h10 = __bfloat162float(__float2bfloat16(v10));
    float h11 = __bfloat162float(__float2bfloat16(v11));
    uint4 f;
    f.x = pack2bf16(h00, h01);
    f.y = pack2bf16(h10, h11);
    f.z = pack2bf16(v00 - h00, v01 - h01);
    f.w = pack2bf16(v10 - h10, v11 - h11);
    out[idx] = f;
}

// ---------------- per-layer: A/B projections, NB nodes per block; zero agg ----------------
__global__ void __launch_bounds__(128) ab_kernel(
    const float* __restrict__ hf, const float* __restrict__ w1,
    float* __restrict__ A, float* __restrict__ B,
    float* __restrict__ aggm, float* __restrict__ aggx) {
    __shared__ float hs[NB][H];
    int i0 = blockIdx.x * NB, k = threadIdx.x;
    #pragma unroll
    for (int n = 0; n < NB; n++) {
        hs[n][k] = hf[(size_t)(i0 + n) * H + k];
        aggm[(size_t)(i0 + n) * H + k] = 0.f;
    }
    if (k < 3 * NB) aggx[i0 * 3 + k] = 0.f;
    __syncthreads();
    float a[NB], b[NB];
    #pragma unroll
    for (int n = 0; n < NB; n++) { a[n] = 0.f; b[n] = 0.f; }
    for (int j = 0; j < H; j += 4) {
        float wa0 = w1[(j + 0) * H + k], wa1 = w1[(j + 1) * H + k];
        float wa2 = w1[(j + 2) * H + k], wa3 = w1[(j + 3) * H + k];
        float wb0 = w1[(H + j + 0) * H + k], wb1 = w1[(H + j + 1) * H + k];
        float wb2 = w1[(H + j + 2) * H + k], wb3 = w1[(H + j + 3) * H + k];
        #pragma unroll
        for (int n = 0; n < NB; n++) {
            float4 v = *reinterpret_cast<const float4*>(&hs[n][j]);
            a[n] = fmaf(v.x, wa0, a[n]); a[n] = fmaf(v.y, wa1, a[n]);
            a[n] = fmaf(v.z, wa2, a[n]); a[n] = fmaf(v.w, wa3, a[n]);
            b[n] = fmaf(v.x, wb0, b[n]); b[n] = fmaf(v.y, wb1, b[n]);
            b[n] = fmaf(v.z, wb2, b[n]); b[n] = fmaf(v.w, wb3, b[n]);
        }
    }
    #pragma unroll
    for (int n = 0; n < NB; n++) {
        A[(size_t)(i0 + n) * H + k] = a[n];
        B[(size_t)(i0 + n) * H + k] = b[n];
    }
}

// ---------------- edge kernel: warp-MMA, B frags from global ----------------
#define ASTRIDE 272   // bytes per A row (136 bf16, conflict-free ldmatrix)
#define SM_AHI   0
#define SM_ALO   34816
#define SM_EAS   69632
#define SM_MS    77824
#define SM_B2    86016
#define SM_CB    86528
#define SM_C2    87040
#define SM_C0    87552
#define SM_W1D   88064
#define SM_DIFF  88576
#define SM_DSQ   90112
#define SM_ROW   90624
#define SM_COL   91136
#define SM_SPART 91648
#define SMEM_EDGE_TOTAL 92160

extern "C" __global__ void __launch_bounds__(256, 2) edge_kernel(
    const int* __restrict__ row, const int* __restrict__ col,
    const float* __restrict__ x,
    const float* __restrict__ Ag, const float* __restrict__ Bg,
    const float* __restrict__ ea,
    const float* __restrict__ Mg, const float* __restrict__ c0g,
    const float* __restrict__ w1d,
    const float* __restrict__ b2, const float* __restrict__ cb,
    const float* __restrict__ c2,
    const uint4* __restrict__ w2f, const uint4* __restrict__ c1f,
    float* __restrict__ aggm, float* __restrict__ aggx) {
    extern __shared__ unsigned char smem[];
    const uint32_t smem_base = smem_u32(smem);
    int tid = threadIdx.x;
    int wid = tid >> 5, lane = tid & 31;
    int g = lane >> 2, tig = lane & 3;
    int k = tid & 127, eh = tid >> 7;
    int e0 = blockIdx.x * TILE_E;

    float* Ms    = (float*)(smem + SM_MS);
    float* EAs   = (float*)(smem + SM_EAS);
    float* B2s   = (float*)(smem + SM_B2);
    float* CBs   = (float*)(smem + SM_CB);
    float* C2s   = (float*)(smem + SM_C2);
    float* C0s   = (float*)(smem + SM_C0);
    float* W1Ds  = (float*)(smem + SM_W1D);
    float* DIFFs = (float*)(smem + SM_DIFF);
    float* DSQs  = (float*)(smem + SM_DSQ);
    int*   ROWs  = (int*)(smem + SM_ROW);
    int*   COLs  = (int*)(smem + SM_COL);
    float* SPARTs= (float*)(smem + SM_SPART);
    __nv_bfloat16* AHIb = (__nv_bfloat16*)(smem + SM_AHI);
    __nv_bfloat16* ALOb = (__nv_bfloat16*)(smem + SM_ALO);

    for (int i = tid; i < EDGE_IN * H; i += 256) Ms[i] = Mg[i];
    {
        const float4* src = (const float4*)(ea + (size_t)e0 * EDGE_IN);
        float4* dst = (float4*)EAs;
        for (int i = tid; i < TILE_E * EDGE_IN / 4; i += 256) dst[i] = src[i];
    }
    if (tid < H) {
        B2s[tid] = b2[tid]; CBs[tid] = cb[tid]; C2s[tid] = c2[tid];
        C0s[tid] = c0g[tid]; W1Ds[tid] = w1d[tid];
    }
    if (tid < TILE_E) {
        int e = e0 + tid;
        int r = row[e], c = col[e];
        ROWs[tid] = r; COLs[tid] = c;
        float dx = x[r * 3 + 0] - x[c * 3 + 0];
        float dy = x[r * 3 + 1] - x[c * 3 + 1];
        float dz = x[r * 3 + 2] - x[c * 3 + 2];
        DIFFs[tid * 3 + 0] = dx; DIFFs[tid * 3 + 1] = dy; DIFFs[tid * 3 + 2] = dz;
        DSQs[tid] = dx * dx + dy * dy + dz * dz;
    }
    __syncthreads();

    // build hidden tile: silu(A[r] + B[c] + c0 + dsq*w1d + ea@M), split bf16 hi/lo
    {
        float c0k = C0s[k], w1dk = W1Ds[k];
        #pragma unroll 2
        for (int e = eh; e < TILE_E; e += 2) {
            int r = ROWs[e], c = COLs[e];
            float pre = Ag[(size_t)r * H + k] + Bg[(size_t)c * H + k]
                      + c0k + DSQs[e] * w1dk;
            const float4* eav = (const float4*)&EAs[e * EDGE_IN];
            float4 v0 = eav[0], v1 = eav[1], v2 = eav[2], v3 = eav[3];
            pre = fmaf(v0.x, Ms[0 * H + k], pre);  pre = fmaf(v0.y, Ms[1 * H + k], pre);
            pre = fmaf(v0.z, Ms[2 * H + k], pre);  pre = fmaf(v0.w, Ms[3 * H + k], pre);
            pre = fmaf(v1.x, Ms[4 * H + k], pre);  pre = fmaf(v1.y, Ms[5 * H + k], pre);
            pre = fmaf(v1.z, Ms[6 * H + k], pre);  pre = fmaf(v1.w, Ms[7 * H + k], pre);
            pre = fmaf(v2.x, Ms[8 * H + k], pre);  pre = fmaf(v2.y, Ms[9 * H + k], pre);
            pre = fmaf(v2.z, Ms[10 * H + k], pre); pre = fmaf(v2.w, Ms[11 * H + k], pre);
            pre = fmaf(v3.x, Ms[12 * H + k], pre); pre = fmaf(v3.y, Ms[13 * H + k], pre);
            pre = fmaf(v3.z, Ms[14 * H + k], pre); pre = fmaf(v3.w, Ms[15 * H + k], pre);
            float hv = silu_f(pre);
            __nv_bfloat16 hh = __float2bfloat16(hv);
            __nv_bfloat16 hl = __float2bfloat16(hv - __bfloat162float(hh));
            AHIb[e * 136 + k] = hh;
            ALOb[e * 136 + k] = hl;
        }
    }
    __syncthreads();

    uint32_t aRowOff = (uint32_t)((16 * wid + (lane & 15)) * ASTRIDE + (lane >> 4) * 16);
    int e_lo = 16 * wid + g, e_hi = e_lo + 8;
    int r_lo = ROWs[e_lo], r_hi = ROWs[e_hi];

    float d[16][4];

    // ---------------- GEMM1: D = hidden @ w2 ----------------
    #pragma unroll
    for (int nt = 0; nt < 16; nt++) { d[nt][0] = d[nt][1] = d[nt][2] = d[nt][3] = 0.f; }
    for (int kt = 0; kt < 8; kt++) {
        uint32_t ahi[4], alo[4];
        ldsm_x4(ahi, smem_base + SM_AHI + aRowOff + kt * 32);
        ldsm_x4(alo, smem_base + SM_ALO + aRowOff + kt * 32);
        const uint4* wk = w2f + kt * 512 + lane;
        #pragma unroll
        for (int nt = 0; nt < 16; nt++) {
            uint4 f = wk[nt * 32];
            mma16816(d[nt], ahi, f.x, f.y);
            mma16816(d[nt], alo, f.x, f.y);
            mma16816(d[nt], ahi, f.z, f.w);
        }
    }

    // epilogue1: m = silu(D + b2); write hi/lo to own A rows; fused aggm atomics
    #pragma unroll
    for (int nt = 0; nt < 16; nt++) {
        int ch0 = nt * 8 + 2 * tig;
        float b0 = B2s[ch0], b1v = B2s[ch0 + 1];
        float m00 = silu_f(d[nt][0] + b0);
        float m01 = silu_f(d[nt][1] + b1v);
        float m10 = silu_f(d[nt][2] + b0);
        float m11 = silu_f(d[nt][3] + b1v);
        float h00 = __bfloat162float(__float2bfloat16(m00));
        float h01 = __bfloat162float(__float2bfloat16(m01));
        float h10 = __bfloat162float(__float2bfloat16(m10));
        float h11 = __bfloat162float(__float2bfloat16(m11));
        *(uint32_t*)(smem + SM_AHI + e_lo * ASTRIDE + ch0 * 2) = pack2bf16(h00, h01);
        *(uint32_t*)(smem + SM_AHI + e_hi * ASTRIDE + ch0 * 2) = pack2bf16(h10, h11);
        *(uint32_t*)(smem + SM_ALO + e_lo * ASTRIDE + ch0 * 2) = pack2bf16(m00 - h00, m01 - h01);
        *(uint32_t*)(smem + SM_ALO + e_hi * ASTRIDE + ch0 * 2) = pack2bf16(m10 - h10, m11 - h11);
        atomicAdd(aggm + (size_t)r_lo * H + ch0, m00);
        atomicAdd(aggm + (size_t)r_lo * H + ch0 + 1, m01);
        atomicAdd(aggm + (size_t)r_hi * H + ch0, m10);
        atomicAdd(aggm + (size_t)r_hi * H + ch0 + 1, m11);
    }
    __syncwarp();   // A rows are warp-private: warp-local ordering suffices

    // ---------------- GEMM2: D = m @ c1 ----------------
    #pragma unroll
    for (int nt = 0; nt < 16; nt++) { d[nt][0] = d[nt][1] = d[nt][2] = d[nt][3] = 0.f; }
    for (int kt = 0; kt < 8; kt++) {
        uint32_t ahi[4], alo[4];
        ldsm_x4(ahi, smem_base + SM_AHI + aRowOff + kt * 32);
        ldsm_x4(alo, smem_base + SM_ALO + aRowOff + kt * 32);
        const uint4* wk = c1f + kt * 512 + lane;
        #pragma unroll
        for (int nt = 0; nt < 16; nt++) {
            uint4 f = wk[nt * 32];
            mma16816(d[nt], ahi, f.x, f.y);
            mma16816(d[nt], alo, f.x, f.y);
            mma16816(d[nt], ahi, f.z, f.w);
        }
    }

    // epilogue2: per-edge s = sum_ch silu(D + cb) * c2
    {
        float sLow = 0.f, sHigh = 0.f;
        #pragma unroll
        for (int nt = 0; nt < 16; nt++) {
            int ch0 = nt * 8 + 2 * tig;
            float cb0 = CBs[ch0], cb1 = CBs[ch0 + 1];
            float cc0 = C2s[ch0], cc1 = C2s[ch0 + 1];
            sLow  = fmaf(silu_f(d[nt][0] + cb0), cc0, sLow);
            sLow  = fmaf(silu_f(d[nt][1] + cb1), cc1, sLow);
            sHigh = fmaf(silu_f(d[nt][2] + cb0), cc0, sHigh);
            sHigh = fmaf(silu_f(d[nt][3] + cb1), cc1, sHigh);
        }
        sLow += __shfl_xor_sync(0xffffffffu, sLow, 1);
        sLow += __shfl_xor_sync(0xffffffffu, sLow, 2);
        sHigh += __shfl_xor_sync(0xffffffffu, sHigh, 1);
        sHigh += __shfl_xor_sync(0xffffffffu, sHigh, 2);
        if (tig == 0) {
            SPARTs[16 * wid + g] = sLow;
            SPARTs[16 * wid + 8 + g] = sHigh;
        }
    }
    __syncthreads();

    if (tid < TILE_E) {
        float wv = tanhf(SPARTs[tid]);
        float dist = sqrtf(DSQs[tid] + EPS_F);
        float inv = wv / (dist + EPS_F);
        int r = ROWs[tid];
        atomicAdd(&aggx[r * 3 + 0], DIFFs[tid * 3 + 0] * inv);
        atomicAdd(&aggx[r * 3 + 1], DIFFs[tid * 3 + 1] * inv);
        atomicAdd(&aggx[r * 3 + 2], DIFFs[tid * 3 + 2] * inv);
    }
}

// ---------------- per-layer node update, NB nodes per block ----------------
__global__ void __launch_bounds__(128) node_update_kernel(
    float* __restrict__ hf, const float* __restrict__ aggm,
    float* __restrict__ xb, const float* __restrict__ aggx,
    const float* __restrict__ mask,
    const float* __restrict__ n1, const float* __restrict__ nb1,
    const float* __restrict__ n2, const float* __restrict__ nb2) {
    __shared__ float ins[NB][2 * H];
    __shared__ float hid[NB][H];
    int i0 = blockIdx.x * NB, k = threadIdx.x;
    #pragma unroll
    for (int n = 0; n < NB; n++) {
        ins[n][k] = hf[(size_t)(i0 + n) * H + k];
        ins[n][H + k] = aggm[(size_t)(i0 + n) * H + k];
    }
    __syncthreads();
    float a[NB];
    {
        float nb = nb1[k];
        #pragma unroll
        for (int n = 0; n < NB; n++) a[n] = nb;
    }
    for (int j = 0; j < 2 * H; j += 4) {
        float w0 = n1[(j + 0) * H + k], w1v = n1[(j + 1) * H + k];
        float w2v = n1[(j + 2) * H + k], w3 = n1[(j + 3) * H + k];
        #pragma unroll
        for (int n = 0; n < NB; n++) {
            float4 v = *reinterpret_cast<const float4*>(&ins[n][j]);
            a[n] = fmaf(v.x, w0, a[n]); a[n] = fmaf(v.y, w1v, a[n]);
            a[n] = fmaf(v.z, w2v, a[n]); a[n] = fmaf(v.w, w3, a[n]);
        }
    }
    #pragma unroll
    for (int n = 0; n < NB; n++) hid[n][k] = silu_f(a[n]);
    __syncthreads();
    float b[NB];
    {
        float nb = nb2[k];
        #pragma unroll
        for (int n = 0; n < NB; n++) b[n] = nb;
    }
    for (int j = 0; j < H; j += 4) {
        float w0 = n2[(j + 0) * H + k], w1v = n2[(j + 1) * H + k];
        float w2v = n2[(j + 2) * H + k], w3 = n2[(j + 3) * H + k];
        #pragma unroll
        for (int n = 0; n < NB; n++) {
            float4 v = *reinterpret_cast<const float4*>(&hid[n][j]);
            b[n] = fmaf(v.x, w0, b[n]); b[n] = fmaf(v.y, w1v, b[n]);
            b[n] = fmaf(v.z, w2v, b[n]); b[n] = fmaf(v.w, w3, b[n]);
        }
    }
    #pragma unroll
    for (int n = 0; n < NB; n++)
        hf[(size_t)(i0 + n) * H + k] = ins[n][k] + b[n];
    if (k < 3 * NB) {
        int n = k / 3;
        xb[i0 * 3 + k] += aggx[i0 * 3 + k] * mask[i0 + n];
    }
}

// ---------------- final velocity ----------------
__global__ void v_kernel(const float* __restrict__ xb, const float* __restrict__ x_in,
                         const float* __restrict__ mask, float* __restrict__ out) {
    int idx = blockIdx.x * blockDim.x + threadIdx.x;
    if (idx < N_NODES * 3) {
        int i = idx / 3;
        out[idx] = (xb[idx] - x_in[idx]) * mask[i];
    }
}

extern "C" void kernel_launch(void* const* d_in, const int* in_sizes, int n_in,
                              void* d_out, int out_size) {
    const float* h        = (const float*)d_in[0];
    const float* x        = (const float*)d_in[1];
    const int*   ei       = (const int*)d_in[2];
    const float* ea       = (const float*)d_in[3];
    const float* t        = (const float*)d_in[4];
    const float* mask     = (const float*)d_in[5];
    const float* tw1      = (const float*)d_in[6];
    const float* tb1      = (const float*)d_in[7];
    const float* tw2      = (const float*)d_in[8];
    const float* tb2      = (const float*)d_in[9];
    const float* new_     = (const float*)d_in[10];
    const float* neb      = (const float*)d_in[11];
    const float* eew      = (const float*)d_in[12];
    const float* eeb      = (const float*)d_in[13];
    const float* ew1      = (const float*)d_in[14];
    const float* eb1      = (const float*)d_in[15];
    const float* ew2      = (const float*)d_in[16];
    const float* eb2      = (const float*)d_in[17];
    const float* cw1      = (const float*)d_in[18];
    const float* cb1      = (const float*)d_in[19];
    const float* cw2      = (const float*)d_in[20];
    const float* nw1      = (const float*)d_in[21];
    const float* nb1      = (const float*)d_in[22];
    const float* nw2      = (const float*)d_in[23];
    const float* nb2      = (const float*)d_in[24];
    float* out = (float*)d_out;

    float *temb, *hfeat, *Ab, *Bb, *xb, *aggm, *aggx, *Mb, *c0b;
    uint4 *w2f, *c1f;
    cudaGetSymbolAddress((void**)&temb,  g_temb);
    cudaGetSymbolAddress((void**)&hfeat, g_hfeat);
    cudaGetSymbolAddress((void**)&Ab,    g_A);
    cudaGetSymbolAddress((void**)&Bb,    g_B);
    cudaGetSymbolAddress((void**)&xb,    g_x);
    cudaGetSymbolAddress((void**)&aggm,  g_aggm);
    cudaGetSymbolAddress((void**)&aggx,  g_aggx);
    cudaGetSymbolAddress((void**)&Mb,    g_M);
    cudaGetSymbolAddress((void**)&c0b,   g_c0);
    cudaGetSymbolAddress((void**)&w2f,   g_w2f);
    cudaGetSymbolAddress((void**)&c1f,   g_c1f);

    cudaFuncSetAttribute(edge_kernel, cudaFuncAttributeMaxDynamicSharedMemorySize,
                         SMEM_EDGE_TOTAL);

    time_emb_kernel<<<1, H>>>(t, tw1, tb1, tw2, tb2, temb);
    node_embed_kernel<<<N_NODES, H>>>(h, new_, neb, temb, x, hfeat, xb);
    prep_kernel<<<L_LAYERS, H>>>(eew, eeb, ew1, eb1, Mb, c0b);
    prep_w_kernel<<<2 * L_LAYERS * 32, 128>>>(ew2, cw1);

    for (int l = 0; l < L_LAYERS; l++) {
        const float* w1  = ew1 + (size_t)l * 385 * H;
        const float* b2  = eb2 + l * H;
        const float* cb  = cb1 + l * H;
        const float* c2  = cw2 + l * H;
        const float* n1  = nw1 + (size_t)l * 2 * H * H;
        const float* nb1l = nb1 + l * H;
        const float* n2  = nw2 + (size_t)l * H * H;
        const float* nb2l = nb2 + l * H;

        ab_kernel<<<N_NODES / NB, H>>>(hfeat, w1, Ab, Bb, aggm, aggx);
        edge_kernel<<<N_EDGES / TILE_E, 256, SMEM_EDGE_TOTAL>>>(
            ei, ei + N_EDGES, xb, Ab, Bb, ea, Mb + l * EDGE_IN * H, c0b + l * H,
            w1 + 256 * H, b2, cb, c2, w2f + l * 4096, c1f + l * 4096,
            aggm, aggx);
        node_update_kernel<<<N_NODES / NB, H>>>(hfeat, aggm, xb, aggx, mask,
                                                n1, nb1l, n2, nb2l);
    }
    v_kernel<<<(N_NODES * 3 + 127) / 128, 128>>>(xb, x, mask, out);
}

// round 8
// speedup vs baseline: 2.1287x; 1.4148x over previous
#include <cuda_runtime.h>
#include <cuda_bf16.h>
#include <math.h>
#include <stdint.h>

#define N_NODES 10000
#define N_EDGES 320000
#define H 128
#define NODE_IN 64
#define EDGE_IN 16
#define L_LAYERS 4
#define EPS_F 1e-8f
#define TILE_E 128
#define NB 8

// ---------------- scratch (device globals; no allocation allowed) ----------------
__device__ float g_hfeat[N_NODES * H];
__device__ float g_A[N_NODES * H];
__device__ float g_B[N_NODES * H];
__device__ float g_x[N_NODES * 3];
__device__ float g_aggm[N_NODES * H];
__device__ float g_aggx[N_NODES * 3];
__device__ float g_M[L_LAYERS * EDGE_IN * H];   // folded low-rank edge weights
__device__ float g_c0[L_LAYERS * H];            // folded biases
// B fragments in MMA order: [layer][kt(8)][nt(16)][lane(32)] -> uint4 {bhi0,bhi1,blo0,blo1}
__device__ uint4 g_w2f[L_LAYERS * 4096];
__device__ uint4 g_c1f[L_LAYERS * 4096];

__device__ __forceinline__ float silu_f(float v) {
    return v / (1.0f + __expf(-v));
}

__device__ __forceinline__ uint32_t smem_u32(const void* p) {
    uint32_t a;
    asm("{ .reg .u64 t; cvta.to.shared.u64 t, %1; cvt.u32.u64 %0, t; }" : "=r"(a) : "l"(p));
    return a;
}

__device__ __forceinline__ void ldsm_x4(uint32_t* r, uint32_t addr) {
    asm volatile("ldmatrix.sync.aligned.m8n8.x4.shared.b16 {%0,%1,%2,%3}, [%4];"
        : "=r"(r[0]), "=r"(r[1]), "=r"(r[2]), "=r"(r[3]) : "r"(addr));
}
__device__ __forceinline__ void mma16816(float* d, const uint32_t* a, uint32_t b0, uint32_t b1) {
    asm volatile("mma.sync.aligned.m16n8k16.row.col.f32.bf16.bf16.f32 "
        "{%0,%1,%2,%3}, {%4,%5,%6,%7}, {%8,%9}, {%0,%1,%2,%3};"
        : "+f"(d[0]), "+f"(d[1]), "+f"(d[2]), "+f"(d[3])
        : "r"(a[0]), "r"(a[1]), "r"(a[2]), "r"(a[3]), "r"(b0), "r"(b1));
}
__device__ __forceinline__ void red_add_v2(float* addr, float a, float b) {
    asm volatile("red.global.add.v2.f32 [%0], {%1, %2};"
        :: "l"(addr), "f"(a), "f"(b) : "memory");
}
__device__ __forceinline__ uint32_t pack2bf16(float a, float b) {
    uint32_t ua = (uint32_t)__bfloat16_as_ushort(__float2bfloat16(a));
    uint32_t ub = (uint32_t)__bfloat16_as_ushort(__float2bfloat16(b));
    return ua | (ub << 16);
}

// ---------------- node embedding (t-embedding fused in) + x init ----------------
__global__ void __launch_bounds__(128) node_embed_kernel(
    const float* __restrict__ h, const float* __restrict__ W, const float* __restrict__ b,
    const float* __restrict__ t,
    const float* __restrict__ tw1, const float* __restrict__ tb1,
    const float* __restrict__ tw2, const float* __restrict__ tb2,
    const float* __restrict__ x_in,
    float* __restrict__ hf, float* __restrict__ xb) {
    __shared__ float hs[NB][NODE_IN];
    __shared__ float h1[H];
    int i0 = blockIdx.x * NB, k = threadIdx.x;
    h1[k] = silu_f(t[0] * tw1[k] + tb1[k]);
    {
        const float* hsrc = h + (size_t)i0 * NODE_IN;
        for (int i = k; i < NB * NODE_IN; i += 128) (&hs[0][0])[i] = hsrc[i];
    }
    __syncthreads();
    float te = tb2[k] + b[k];
    for (int j = 0; j < H; j += 4) {
        float4 v = *reinterpret_cast<const float4*>(&h1[j]);
        te = fmaf(v.x, tw2[(j + 0) * H + k], te);
        te = fmaf(v.y, tw2[(j + 1) * H + k], te);
        te = fmaf(v.z, tw2[(j + 2) * H + k], te);
        te = fmaf(v.w, tw2[(j + 3) * H + k], te);
    }
    float acc[NB];
    #pragma unroll
    for (int n = 0; n < NB; n++) acc[n] = te;
    for (int j = 0; j < NODE_IN; j += 4) {
        float w0 = W[(j + 0) * H + k], w1v = W[(j + 1) * H + k];
        float w2v = W[(j + 2) * H + k], w3 = W[(j + 3) * H + k];
        #pragma unroll
        for (int n = 0; n < NB; n++) {
            float4 v = *reinterpret_cast<const float4*>(&hs[n][j]);
            acc[n] = fmaf(v.x, w0, acc[n]); acc[n] = fmaf(v.y, w1v, acc[n]);
            acc[n] = fmaf(v.z, w2v, acc[n]); acc[n] = fmaf(v.w, w3, acc[n]);
        }
    }
    #pragma unroll
    for (int n = 0; n < NB; n++) hf[(size_t)(i0 + n) * H + k] = acc[n];
    if (k < 3 * NB) xb[i0 * 3 + k] = x_in[i0 * 3 + k];
}

// ---------------- fused prep: fold M/c0 (blocks 0..3) + w2/c1 MMA frags (blocks 4..259) ----
__global__ void prep_all_kernel(const float* __restrict__ eew, const float* __restrict__ eeb,
                                const float* __restrict__ ew1, const float* __restrict__ eb1,
                                const float* __restrict__ ew2, const float* __restrict__ cw1,
                                float* __restrict__ M, float* __restrict__ c0) {
    int k = threadIdx.x;
    if (blockIdx.x < L_LAYERS) {
        __shared__ float es[EDGE_IN][H];
        __shared__ float ebs[H];
        int l = blockIdx.x;
        const float* w1c = ew1 + (size_t)l * 385 * H + 257 * H;
        const float* b1 = eb1 + l * H;
        #pragma unroll
        for (int i = 0; i < EDGE_IN; i++) es[i][k] = eew[i * H + k];
        ebs[k] = eeb[k];
        __syncthreads();
        float m[EDGE_IN];
        #pragma unroll
        for (int i = 0; i < EDGE_IN; i++) m[i] = 0.f;
        float c = b1[k];
        for (int j = 0; j < H; j++) {
            float w = w1c[j * H + k];
            c = fmaf(ebs[j], w, c);
            #pragma unroll
            for (int i = 0; i < EDGE_IN; i++) m[i] = fmaf(es[i][j], w, m[i]);
        }
        #pragma unroll
        for (int i = 0; i < EDGE_IN; i++) M[l * EDGE_IN * H + i * H + k] = m[i];
        c0[l * H + k] = c;
    } else {
        int idx2 = blockIdx.x - L_LAYERS;
        int mat = idx2 >> 7;
        int l = (idx2 >> 5) & 3;
        int idx = (idx2 & 31) * 128 + k;
        const float* W = (mat == 0) ? (ew2 + (size_t)l * H * H) : (cw1 + (size_t)l * H * H);
        uint4* out = ((mat == 0) ? g_w2f : g_c1f) + l * 4096;
        int kt = idx >> 9;
        int nt = (idx >> 5) & 15;
        int lane = idx & 31;
        int n = nt * 8 + (lane >> 2);
        int k0 = kt * 16 + 2 * (lane & 3);
        float v00 = W[(k0 + 0) * H + n], v01 = W[(k0 + 1) * H + n];
        float v10 = W[(k0 + 8) * H + n], v11 = W[(k0 + 9) * H + n];
        float h00 = __bfloat162float(__float2bfloat16(v00));
        float h01 = __bfloat162float(__float2bfloat16(v01));
        float h10 = __bfloat162float(__float2bfloat16(v10));
        float h11 = __bfloat162float(__float2bfloat16(v11));
        uint4 f;
        f.x = pack2bf16(h00, h01);
        f.y = pack2bf16(h10, h11);
        f.z = pack2bf16(v00 - h00, v01 - h01);
        f.w = pack2bf16(v10 - h10, v11 - h11);
        out[idx] = f;
    }
}

// ---------------- per-layer: A/B projections, NB nodes per block; zero agg ----------------
__global__ void __launch_bounds__(128) ab_kernel(
    const float* __restrict__ hf, const float* __restrict__ w1,
    float* __restrict__ A, float* __restrict__ B,
    float* __restrict__ aggm, float* __restrict__ aggx) {
    __shared__ float hs[NB][H];
    int i0 = blockIdx.x * NB, k = threadIdx.x;
    #pragma unroll
    for (int n = 0; n < NB; n++) {
        hs[n][k] = hf[(size_t)(i0 + n) * H + k];
        aggm[(size_t)(i0 + n) * H + k] = 0.f;
    }
    if (k < 3 * NB) aggx[i0 * 3 + k] = 0.f;
    __syncthreads();
    float a[NB], b[NB];
    #pragma unroll
    for (int n = 0; n < NB; n++) { a[n] = 0.f; b[n] = 0.f; }
    for (int j = 0; j < H; j += 4) {
        float wa0 = w1[(j + 0) * H + k], wa1 = w1[(j + 1) * H + k];
        float wa2 = w1[(j + 2) * H + k], wa3 = w1[(j + 3) * H + k];
        float wb0 = w1[(H + j + 0) * H + k], wb1 = w1[(H + j + 1) * H + k];
        float wb2 = w1[(H + j + 2) * H + k], wb3 = w1[(H + j + 3) * H + k];
        #pragma unroll
        for (int n = 0; n < NB; n++) {
            float4 v = *reinterpret_cast<const float4*>(&hs[n][j]);
            a[n] = fmaf(v.x, wa0, a[n]); a[n] = fmaf(v.y, wa1, a[n]);
            a[n] = fmaf(v.z, wa2, a[n]); a[n] = fmaf(v.w, wa3, a[n]);
            b[n] = fmaf(v.x, wb0, b[n]); b[n] = fmaf(v.y, wb1, b[n]);
            b[n] = fmaf(v.z, wb2, b[n]); b[n] = fmaf(v.w, wb3, b[n]);
        }
    }
    #pragma unroll
    for (int n = 0; n < NB; n++) {
        A[(size_t)(i0 + n) * H + k] = a[n];
        B[(size_t)(i0 + n) * H + k] = b[n];
    }
}

// ---------------- edge kernel: warp-MMA, register-chained GEMM2 ----------------
#define ASTRIDE 272   // bytes per A row (136 bf16, conflict-free ldmatrix)
#define SM_AHI   0
#define SM_ALO   34816
#define SM_EAS   69632
#define SM_MS    77824
#define SM_B2    86016
#define SM_CB    86528
#define SM_C2    87040
#define SM_C0    87552
#define SM_W1D   88064
#define SM_DIFF  88576
#define SM_DSQ   90112
#define SM_ROW   90624
#define SM_COL   91136
#define SM_SPART 91648
#define SMEM_EDGE_TOTAL 92160

extern "C" __global__ void __launch_bounds__(256, 2) edge_kernel(
    const int* __restrict__ row, const int* __restrict__ col,
    const float* __restrict__ x,
    const float* __restrict__ Ag, const float* __restrict__ Bg,
    const float* __restrict__ ea,
    const float* __restrict__ Mg, const float* __restrict__ c0g,
    const float* __restrict__ w1d,
    const float* __restrict__ b2, const float* __restrict__ cb,
    const float* __restrict__ c2,
    const uint4* __restrict__ w2f, const uint4* __restrict__ c1f,
    float* __restrict__ aggm, float* __restrict__ aggx) {
    extern __shared__ unsigned char smem[];
    const uint32_t smem_base = smem_u32(smem);
    int tid = threadIdx.x;
    int wid = tid >> 5, lane = tid & 31;
    int g = lane >> 2, tig = lane & 3;
    int k = tid & 127, eh = tid >> 7;
    int e0 = blockIdx.x * TILE_E;

    float* Ms    = (float*)(smem + SM_MS);
    float* EAs   = (float*)(smem + SM_EAS);
    float* B2s   = (float*)(smem + SM_B2);
    float* CBs   = (float*)(smem + SM_CB);
    float* C2s   = (float*)(smem + SM_C2);
    float* C0s   = (float*)(smem + SM_C0);
    float* W1Ds  = (float*)(smem + SM_W1D);
    float* DIFFs = (float*)(smem + SM_DIFF);
    float* DSQs  = (float*)(smem + SM_DSQ);
    int*   ROWs  = (int*)(smem + SM_ROW);
    int*   COLs  = (int*)(smem + SM_COL);
    float* SPARTs= (float*)(smem + SM_SPART);
    __nv_bfloat16* AHIb = (__nv_bfloat16*)(smem + SM_AHI);
    __nv_bfloat16* ALOb = (__nv_bfloat16*)(smem + SM_ALO);

    for (int i = tid; i < EDGE_IN * H; i += 256) Ms[i] = Mg[i];
    {
        const float4* src = (const float4*)(ea + (size_t)e0 * EDGE_IN);
        float4* dst = (float4*)EAs;
        for (int i = tid; i < TILE_E * EDGE_IN / 4; i += 256) dst[i] = src[i];
    }
    if (tid < H) {
        B2s[tid] = b2[tid]; CBs[tid] = cb[tid]; C2s[tid] = c2[tid];
        C0s[tid] = c0g[tid]; W1Ds[tid] = w1d[tid];
    }
    if (tid < TILE_E) {
        int e = e0 + tid;
        int r = row[e], c = col[e];
        ROWs[tid] = r; COLs[tid] = c;
        float dx = x[r * 3 + 0] - x[c * 3 + 0];
        float dy = x[r * 3 + 1] - x[c * 3 + 1];
        float dz = x[r * 3 + 2] - x[c * 3 + 2];
        DIFFs[tid * 3 + 0] = dx; DIFFs[tid * 3 + 1] = dy; DIFFs[tid * 3 + 2] = dz;
        DSQs[tid] = dx * dx + dy * dy + dz * dz;
    }
    __syncthreads();

    // build hidden tile: silu(A[r] + B[c] + c0 + dsq*w1d + ea@M), split bf16 hi/lo
    {
        float c0k = C0s[k], w1dk = W1Ds[k];
        #pragma unroll 2
        for (int e = eh; e < TILE_E; e += 2) {
            int r = ROWs[e], c = COLs[e];
            float pre = Ag[(size_t)r * H + k] + Bg[(size_t)c * H + k]
                      + c0k + DSQs[e] * w1dk;
            const float4* eav = (const float4*)&EAs[e * EDGE_IN];
            float4 v0 = eav[0], v1 = eav[1], v2 = eav[2], v3 = eav[3];
            pre = fmaf(v0.x, Ms[0 * H + k], pre);  pre = fmaf(v0.y, Ms[1 * H + k], pre);
            pre = fmaf(v0.z, Ms[2 * H + k], pre);  pre = fmaf(v0.w, Ms[3 * H + k], pre);
            pre = fmaf(v1.x, Ms[4 * H + k], pre);  pre = fmaf(v1.y, Ms[5 * H + k], pre);
            pre = fmaf(v1.z, Ms[6 * H + k], pre);  pre = fmaf(v1.w, Ms[7 * H + k], pre);
            pre = fmaf(v2.x, Ms[8 * H + k], pre);  pre = fmaf(v2.y, Ms[9 * H + k], pre);
            pre = fmaf(v2.z, Ms[10 * H + k], pre); pre = fmaf(v2.w, Ms[11 * H + k], pre);
            pre = fmaf(v3.x, Ms[12 * H + k], pre); pre = fmaf(v3.y, Ms[13 * H + k], pre);
            pre = fmaf(v3.z, Ms[14 * H + k], pre); pre = fmaf(v3.w, Ms[15 * H + k], pre);
            float hv = silu_f(pre);
            __nv_bfloat16 hh = __float2bfloat16(hv);
            __nv_bfloat16 hl = __float2bfloat16(hv - __bfloat162float(hh));
            AHIb[e * 136 + k] = hh;
            ALOb[e * 136 + k] = hl;
        }
    }
    __syncthreads();

    uint32_t aRowOff = (uint32_t)((16 * wid + (lane & 15)) * ASTRIDE + (lane >> 4) * 16);
    int e_lo = 16 * wid + g, e_hi = e_lo + 8;
    int r_lo = ROWs[e_lo], r_hi = ROWs[e_hi];

    float d[16][4];

    // ---------------- GEMM1: D = hidden @ w2 ----------------
    #pragma unroll
    for (int nt = 0; nt < 16; nt++) { d[nt][0] = d[nt][1] = d[nt][2] = d[nt][3] = 0.f; }
    for (int kt = 0; kt < 8; kt++) {
        uint32_t ahi[4], alo[4];
        ldsm_x4(ahi, smem_base + SM_AHI + aRowOff + kt * 32);
        ldsm_x4(alo, smem_base + SM_ALO + aRowOff + kt * 32);
        const uint4* wk = w2f + kt * 512 + lane;
        #pragma unroll
        for (int nt = 0; nt < 16; nt++) {
            uint4 f = wk[nt * 32];
            mma16816(d[nt], ahi, f.x, f.y);
            mma16816(d[nt], alo, f.x, f.y);
            mma16816(d[nt], ahi, f.z, f.w);
        }
    }

    // conversion: m = silu(D + b2) -> GEMM2 A-fragments in registers + v2 atomics
    // D cols of nt pair (2j, 2j+1) == A-fragment k-tile j of GEMM2
    uint32_t mhi[8][4], mlo[8][4];
    #pragma unroll
    for (int j = 0; j < 8; j++) {
        int ntA = 2 * j, ntB = 2 * j + 1;
        int chA = ntA * 8 + 2 * tig;
        int chB = ntB * 8 + 2 * tig;
        float bA0 = B2s[chA], bA1 = B2s[chA + 1];
        float bB0 = B2s[chB], bB1 = B2s[chB + 1];
        float mA00 = silu_f(d[ntA][0] + bA0), mA01 = silu_f(d[ntA][1] + bA1);
        float mA10 = silu_f(d[ntA][2] + bA0), mA11 = silu_f(d[ntA][3] + bA1);
        float mB00 = silu_f(d[ntB][0] + bB0), mB01 = silu_f(d[ntB][1] + bB1);
        float mB10 = silu_f(d[ntB][2] + bB0), mB11 = silu_f(d[ntB][3] + bB1);
        float hA00 = __bfloat162float(__float2bfloat16(mA00));
        float hA01 = __bfloat162float(__float2bfloat16(mA01));
        float hA10 = __bfloat162float(__float2bfloat16(mA10));
        float hA11 = __bfloat162float(__float2bfloat16(mA11));
        float hB00 = __bfloat162float(__float2bfloat16(mB00));
        float hB01 = __bfloat162float(__float2bfloat16(mB01));
        float hB10 = __bfloat162float(__float2bfloat16(mB10));
        float hB11 = __bfloat162float(__float2bfloat16(mB11));
        mhi[j][0] = pack2bf16(hA00, hA01); mlo[j][0] = pack2bf16(mA00 - hA00, mA01 - hA01);
        mhi[j][1] = pack2bf16(hA10, hA11); mlo[j][1] = pack2bf16(mA10 - hA10, mA11 - hA11);
        mhi[j][2] = pack2bf16(hB00, hB01); mlo[j][2] = pack2bf16(mB00 - hB00, mB01 - hB01);
        mhi[j][3] = pack2bf16(hB10, hB11); mlo[j][3] = pack2bf16(mB10 - hB10, mB11 - hB11);
        red_add_v2(aggm + (size_t)r_lo * H + chA, mA00, mA01);
        red_add_v2(aggm + (size_t)r_hi * H + chA, mA10, mA11);
        red_add_v2(aggm + (size_t)r_lo * H + chB, mB00, mB01);
        red_add_v2(aggm + (size_t)r_hi * H + chB, mB10, mB11);
    }

    // ---------------- GEMM2: D2 = m @ c1, two N-halves, A-frags from registers ----------
    float s_lo = 0.f, s_hi = 0.f;
    #pragma unroll
    for (int nh = 0; nh < 2; nh++) {
        float d2[8][4];
        #pragma unroll
        for (int j2 = 0; j2 < 8; j2++) { d2[j2][0] = d2[j2][1] = d2[j2][2] = d2[j2][3] = 0.f; }
        #pragma unroll
        for (int kt = 0; kt < 8; kt++) {
            const uint4* wk = c1f + kt * 512 + (nh * 8) * 32 + lane;
            #pragma unroll
            for (int j2 = 0; j2 < 8; j2++) {
                uint4 f = wk[j2 * 32];
                mma16816(d2[j2], mhi[kt], f.x, f.y);
                mma16816(d2[j2], mlo[kt], f.x, f.y);
                mma16816(d2[j2], mhi[kt], f.z, f.w);
            }
        }
        #pragma unroll
        for (int j2 = 0; j2 < 8; j2++) {
            int ch0 = (nh * 8 + j2) * 8 + 2 * tig;
            float cb0 = CBs[ch0], cb1 = CBs[ch0 + 1];
            float cc0 = C2s[ch0], cc1 = C2s[ch0 + 1];
            s_lo = fmaf(silu_f(d2[j2][0] + cb0), cc0, s_lo);
            s_lo = fmaf(silu_f(d2[j2][1] + cb1), cc1, s_lo);
            s_hi = fmaf(silu_f(d2[j2][2] + cb0), cc0, s_hi);
            s_hi = fmaf(silu_f(d2[j2][3] + cb1), cc1, s_hi);
        }
    }
    s_lo += __shfl_xor_sync(0xffffffffu, s_lo, 1);
    s_lo += __shfl_xor_sync(0xffffffffu, s_lo, 2);
    s_hi += __shfl_xor_sync(0xffffffffu, s_hi, 1);
    s_hi += __shfl_xor_sync(0xffffffffu, s_hi, 2);
    if (tig == 0) {
        SPARTs[16 * wid + g] = s_lo;
        SPARTs[16 * wid + 8 + g] = s_hi;
    }
    __syncthreads();

    if (tid < TILE_E) {
        float wv = tanhf(SPARTs[tid]);
        float dist = sqrtf(DSQs[tid] + EPS_F);
        float inv = wv / (dist + EPS_F);
        int r = ROWs[tid];
        atomicAdd(&aggx[r * 3 + 0], DIFFs[tid * 3 + 0] * inv);
        atomicAdd(&aggx[r * 3 + 1], DIFFs[tid * 3 + 1] * inv);
        atomicAdd(&aggx[r * 3 + 2], DIFFs[tid * 3 + 2] * inv);
    }
}

// ---------------- per-layer node update, NB nodes per block ----------------
__global__ void __launch_bounds__(128) node_update_kernel(
    float* __restrict__ hf, const float* __restrict__ aggm,
    float* __restrict__ xb, const float* __restrict__ aggx,
    const float* __restrict__ mask,
    const float* __restrict__ n1, const float* __restrict__ nb1,
    const float* __restrict__ n2, const float* __restrict__ nb2) {
    __shared__ float ins[NB][2 * H];
    __shared__ float hid[NB][H];
    int i0 = blockIdx.x * NB, k = threadIdx.x;
    #pragma unroll
    for (int n = 0; n < NB; n++) {
        ins[n][k] = hf[(size_t)(i0 + n) * H + k];
        ins[n][H + k] = aggm[(size_t)(i0 + n) * H + k];
    }
    __syncthreads();
    float a[NB];
    {
        float nb = nb1[k];
        #pragma unroll
        for (int n = 0; n < NB; n++) a[n] = nb;
    }
    for (int j = 0; j < 2 * H; j += 4) {
        float w0 = n1[(j + 0) * H + k], w1v = n1[(j + 1) * H + k];
        float w2v = n1[(j + 2) * H + k], w3 = n1[(j + 3) * H + k];
        #pragma unroll
        for (int n = 0; n < NB; n++) {
            float4 v = *reinterpret_cast<const float4*>(&ins[n][j]);
            a[n] = fmaf(v.x, w0, a[n]); a[n] = fmaf(v.y, w1v, a[n]);
            a[n] = fmaf(v.z, w2v, a[n]); a[n] = fmaf(v.w, w3, a[n]);
        }
    }
    #pragma unroll
    for (int n = 0; n < NB; n++) hid[n][k] = silu_f(a[n]);
    __syncthreads();
    float b[NB];
    {
        float nb = nb2[k];
        #pragma unroll
        for (int n = 0; n < NB; n++) b[n] = nb;
    }
    for (int j = 0; j < H; j += 4) {
        float w0 = n2[(j + 0) * H + k], w1v = n2[(j + 1) * H + k];
        float w2v = n2[(j + 2) * H + k], w3 = n2[(j + 3) * H + k];
        #pragma unroll
        for (int n = 0; n < NB; n++) {
            float4 v = *reinterpret_cast<const float4*>(&hid[n][j]);
            b[n] = fmaf(v.x, w0, b[n]); b[n] = fmaf(v.y, w1v, b[n]);
            b[n] = fmaf(v.z, w2v, b[n]); b[n] = fmaf(v.w, w3, b[n]);
        }
    }
    #pragma unroll
    for (int n = 0; n < NB; n++)
        hf[(size_t)(i0 + n) * H + k] = ins[n][k] + b[n];
    if (k < 3 * NB) {
        int n = k / 3;
        xb[i0 * 3 + k] += aggx[i0 * 3 + k] * mask[i0 + n];
    }
}

// ---------------- final velocity ----------------
__global__ void v_kernel(const float* __restrict__ xb, const float* __restrict__ x_in,
                         const float* __restrict__ mask, float* __restrict__ out) {
    int idx = blockIdx.x * blockDim.x + threadIdx.x;
    if (idx < N_NODES * 3) {
        int i = idx / 3;
        out[idx] = (xb[idx] - x_in[idx]) * mask[i];
    }
}

extern "C" void kernel_launch(void* const* d_in, const int* in_sizes, int n_in,
                              void* d_out, int out_size) {
    const float* h        = (const float*)d_in[0];
    const float* x        = (const float*)d_in[1];
    const int*   ei       = (const int*)d_in[2];
    const float* ea       = (const float*)d_in[3];
    const float* t        = (const float*)d_in[4];
    const float* mask     = (const float*)d_in[5];
    const float* tw1      = (const float*)d_in[6];
    const float* tb1      = (const float*)d_in[7];
    const float* tw2      = (const float*)d_in[8];
    const float* tb2      = (const float*)d_in[9];
    const float* new_     = (const float*)d_in[10];
    const float* neb      = (const float*)d_in[11];
    const float* eew      = (const float*)d_in[12];
    const float* eeb      = (const float*)d_in[13];
    const float* ew1      = (const float*)d_in[14];
    const float* eb1      = (const float*)d_in[15];
    const float* ew2      = (const float*)d_in[16];
    const float* eb2      = (const float*)d_in[17];
    const float* cw1      = (const float*)d_in[18];
    const float* cb1      = (const float*)d_in[19];
    const float* cw2      = (const float*)d_in[20];
    const float* nw1      = (const float*)d_in[21];
    const float* nb1      = (const float*)d_in[22];
    const float* nw2      = (const float*)d_in[23];
    const float* nb2      = (const float*)d_in[24];
    float* out = (float*)d_out;

    float *hfeat, *Ab, *Bb, *xb, *aggm, *aggx, *Mb, *c0b;
    uint4 *w2f, *c1f;
    cudaGetSymbolAddress((void**)&hfeat, g_hfeat);
    cudaGetSymbolAddress((void**)&Ab,    g_A);
    cudaGetSymbolAddress((void**)&Bb,    g_B);
    cudaGetSymbolAddress((void**)&xb,    g_x);
    cudaGetSymbolAddress((void**)&aggm,  g_aggm);
    cudaGetSymbolAddress((void**)&aggx,  g_aggx);
    cudaGetSymbolAddress((void**)&Mb,    g_M);
    cudaGetSymbolAddress((void**)&c0b,   g_c0);
    cudaGetSymbolAddress((void**)&w2f,   g_w2f);
    cudaGetSymbolAddress((void**)&c1f,   g_c1f);

    cudaFuncSetAttribute(edge_kernel, cudaFuncAttributeMaxDynamicSharedMemorySize,
                         SMEM_EDGE_TOTAL);

    node_embed_kernel<<<N_NODES / NB, H>>>(h, new_, neb, t, tw1, tb1, tw2, tb2,
                                           x, hfeat, xb);
    prep_all_kernel<<<L_LAYERS + 256, H>>>(eew, eeb, ew1, eb1, ew2, cw1, Mb, c0b);

    for (int l = 0; l < L_LAYERS; l++) {
        const float* w1  = ew1 + (size_t)l * 385 * H;
        const float* b2  = eb2 + l * H;
        const float* cb  = cb1 + l * H;
        const float* c2  = cw2 + l * H;
        const float* n1  = nw1 + (size_t)l * 2 * H * H;
        const float* nb1l = nb1 + l * H;
        const float* n2  = nw2 + (size_t)l * H * H;
        const float* nb2l = nb2 + l * H;

        ab_kernel<<<N_NODES / NB, H>>>(hfeat, w1, Ab, Bb, aggm, aggx);
        edge_kernel<<<N_EDGES / TILE_E, 256, SMEM_EDGE_TOTAL>>>(
            ei, ei + N_EDGES, xb, Ab, Bb, ea, Mb + l * EDGE_IN * H, c0b + l * H,
            w1 + 256 * H, b2, cb, c2, w2f + l * 4096, c1f + l * 4096,
            aggm, aggx);
        node_update_kernel<<<N_NODES / NB, H>>>(hfeat, aggm, xb, aggx, mask,
                                                n1, nb1l, n2, nb2l);
    }
    v_kernel<<<(N_NODES * 3 + 127) / 128, 128>>>(xb, x, mask, out);
}

// round 9
// speedup vs baseline: 2.2147x; 1.0404x over previous
#include <cuda_runtime.h>
#include <cuda_bf16.h>
#include <math.h>
#include <stdint.h>

#define N_NODES 10000
#define N_EDGES 320000
#define H 128
#define NODE_IN 64
#define EDGE_IN 16
#define L_LAYERS 4
#define EPS_F 1e-8f
#define TILE_E 128
#define NB 8

// ---------------- scratch (device globals; no allocation allowed) ----------------
__device__ float g_hfeat[N_NODES * H];
__device__ float g_A[N_NODES * H];
__device__ float g_B[N_NODES * H];
__device__ float g_x[N_NODES * 3];
__device__ float g_aggm[N_NODES * H];
__device__ float g_aggx[N_NODES * 3];
__device__ float g_M[L_LAYERS * EDGE_IN * H];   // folded low-rank edge weights
__device__ float g_c0[L_LAYERS * H];            // folded biases
// B fragments in MMA order: [layer][kt(8)][nt(16)][lane(32)] -> uint4 {bhi0,bhi1,blo0,blo1}
__device__ uint4 g_w2f[L_LAYERS * 4096];
__device__ uint4 g_c1f[L_LAYERS * 4096];

__device__ __forceinline__ float silu_f(float v) {
    return v / (1.0f + __expf(-v));
}

__device__ __forceinline__ uint32_t smem_u32(const void* p) {
    uint32_t a;
    asm("{ .reg .u64 t; cvta.to.shared.u64 t, %1; cvt.u32.u64 %0, t; }" : "=r"(a) : "l"(p));
    return a;
}

__device__ __forceinline__ void ldsm_x4(uint32_t* r, uint32_t addr) {
    asm volatile("ldmatrix.sync.aligned.m8n8.x4.shared.b16 {%0,%1,%2,%3}, [%4];"
        : "=r"(r[0]), "=r"(r[1]), "=r"(r[2]), "=r"(r[3]) : "r"(addr));
}
__device__ __forceinline__ void mma16816(float* d, const uint32_t* a, uint32_t b0, uint32_t b1) {
    asm volatile("mma.sync.aligned.m16n8k16.row.col.f32.bf16.bf16.f32 "
        "{%0,%1,%2,%3}, {%4,%5,%6,%7}, {%8,%9}, {%0,%1,%2,%3};"
        : "+f"(d[0]), "+f"(d[1]), "+f"(d[2]), "+f"(d[3])
        : "r"(a[0]), "r"(a[1]), "r"(a[2]), "r"(a[3]), "r"(b0), "r"(b1));
}
__device__ __forceinline__ void red_add_v2(float* addr, float a, float b) {
    asm volatile("red.global.add.v2.f32 [%0], {%1, %2};"
        :: "l"(addr), "f"(a), "f"(b) : "memory");
}
__device__ __forceinline__ uint32_t pack2bf16(float a, float b) {
    uint32_t ua = (uint32_t)__bfloat16_as_ushort(__float2bfloat16(a));
    uint32_t ub = (uint32_t)__bfloat16_as_ushort(__float2bfloat16(b));
    return ua | (ub << 16);
}

// ---------------- node embedding (t-embedding fused in) + x init ----------------
__global__ void __launch_bounds__(128) node_embed_kernel(
    const float* __restrict__ h, const float* __restrict__ W, const float* __restrict__ b,
    const float* __restrict__ t,
    const float* __restrict__ tw1, const float* __restrict__ tb1,
    const float* __restrict__ tw2, const float* __restrict__ tb2,
    const float* __restrict__ x_in,
    float* __restrict__ hf, float* __restrict__ xb) {
    __shared__ float hs[NB][NODE_IN];
    __shared__ float h1[H];
    int i0 = blockIdx.x * NB, k = threadIdx.x;
    h1[k] = silu_f(t[0] * tw1[k] + tb1[k]);
    {
        const float* hsrc = h + (size_t)i0 * NODE_IN;
        for (int i = k; i < NB * NODE_IN; i += 128) (&hs[0][0])[i] = hsrc[i];
    }
    __syncthreads();
    float te = tb2[k] + b[k];
    for (int j = 0; j < H; j += 4) {
        float4 v = *reinterpret_cast<const float4*>(&h1[j]);
        te = fmaf(v.x, tw2[(j + 0) * H + k], te);
        te = fmaf(v.y, tw2[(j + 1) * H + k], te);
        te = fmaf(v.z, tw2[(j + 2) * H + k], te);
        te = fmaf(v.w, tw2[(j + 3) * H + k], te);
    }
    float acc[NB];
    #pragma unroll
    for (int n = 0; n < NB; n++) acc[n] = te;
    for (int j = 0; j < NODE_IN; j += 4) {
        float w0 = W[(j + 0) * H + k], w1v = W[(j + 1) * H + k];
        float w2v = W[(j + 2) * H + k], w3 = W[(j + 3) * H + k];
        #pragma unroll
        for (int n = 0; n < NB; n++) {
            float4 v = *reinterpret_cast<const float4*>(&hs[n][j]);
            acc[n] = fmaf(v.x, w0, acc[n]); acc[n] = fmaf(v.y, w1v, acc[n]);
            acc[n] = fmaf(v.z, w2v, acc[n]); acc[n] = fmaf(v.w, w3, acc[n]);
        }
    }
    #pragma unroll
    for (int n = 0; n < NB; n++) hf[(size_t)(i0 + n) * H + k] = acc[n];
    if (k < 3 * NB) xb[i0 * 3 + k] = x_in[i0 * 3 + k];
}

// ---------------- fused prep: fold M/c0 (blocks 0..3) + w2/c1 MMA frags (blocks 4..259) ----
__global__ void prep_all_kernel(const float* __restrict__ eew, const float* __restrict__ eeb,
                                const float* __restrict__ ew1, const float* __restrict__ eb1,
                                const float* __restrict__ ew2, const float* __restrict__ cw1,
                                float* __restrict__ M, float* __restrict__ c0) {
    int k = threadIdx.x;
    if (blockIdx.x < L_LAYERS) {
        __shared__ float es[EDGE_IN][H];
        __shared__ float ebs[H];
        int l = blockIdx.x;
        const float* w1c = ew1 + (size_t)l * 385 * H + 257 * H;
        const float* b1 = eb1 + l * H;
        #pragma unroll
        for (int i = 0; i < EDGE_IN; i++) es[i][k] = eew[i * H + k];
        ebs[k] = eeb[k];
        __syncthreads();
        float m[EDGE_IN];
        #pragma unroll
        for (int i = 0; i < EDGE_IN; i++) m[i] = 0.f;
        float c = b1[k];
        for (int j = 0; j < H; j++) {
            float w = w1c[j * H + k];
            c = fmaf(ebs[j], w, c);
            #pragma unroll
            for (int i = 0; i < EDGE_IN; i++) m[i] = fmaf(es[i][j], w, m[i]);
        }
        #pragma unroll
        for (int i = 0; i < EDGE_IN; i++) M[l * EDGE_IN * H + i * H + k] = m[i];
        c0[l * H + k] = c;
    } else {
        int idx2 = blockIdx.x - L_LAYERS;
        int mat = idx2 >> 7;
        int l = (idx2 >> 5) & 3;
        int idx = (idx2 & 31) * 128 + k;
        const float* W = (mat == 0) ? (ew2 + (size_t)l * H * H) : (cw1 + (size_t)l * H * H);
        uint4* out = ((mat == 0) ? g_w2f : g_c1f) + l * 4096;
        int kt = idx >> 9;
        int nt = (idx >> 5) & 15;
        int lane = idx & 31;
        int n = nt * 8 + (lane >> 2);
        int k0 = kt * 16 + 2 * (lane & 3);
        float v00 = W[(k0 + 0) * H + n], v01 = W[(k0 + 1) * H + n];
        float v10 = W[(k0 + 8) * H + n], v11 = W[(k0 + 9) * H + n];
        float h00 = __bfloat162float(__float2bfloat16(v00));
        float h01 = __bfloat162float(__float2bfloat16(v01));
        float h10 = __bfloat162float(__float2bfloat16(v10));
        float h11 = __bfloat162float(__float2bfloat16(v11));
        uint4 f;
        f.x = pack2bf16(h00, h01);
        f.y = pack2bf16(h10, h11);
        f.z = pack2bf16(v00 - h00, v01 - h01);
        f.w = pack2bf16(v10 - h10, v11 - h11);
        out[idx] = f;
    }
}

// ---------------- per-layer: A/B projections, NB nodes per block; zero agg ----------------
__global__ void __launch_bounds__(128) ab_kernel(
    const float* __restrict__ hf, const float* __restrict__ w1,
    float* __restrict__ A, float* __restrict__ B,
    float* __restrict__ aggm, float* __restrict__ aggx) {
    __shared__ float hs[NB][H];
    int i0 = blockIdx.x * NB, k = threadIdx.x;
    #pragma unroll
    for (int n = 0; n < NB; n++) {
        hs[n][k] = hf[(size_t)(i0 + n) * H + k];
        aggm[(size_t)(i0 + n) * H + k] = 0.f;
    }
    if (k < 3 * NB) aggx[i0 * 3 + k] = 0.f;
    __syncthreads();
    float a[NB], b[NB];
    #pragma unroll
    for (int n = 0; n < NB; n++) { a[n] = 0.f; b[n] = 0.f; }
    for (int j = 0; j < H; j += 4) {
        float wa0 = w1[(j + 0) * H + k], wa1 = w1[(j + 1) * H + k];
        float wa2 = w1[(j + 2) * H + k], wa3 = w1[(j + 3) * H + k];
        float wb0 = w1[(H + j + 0) * H + k], wb1 = w1[(H + j + 1) * H + k];
        float wb2 = w1[(H + j + 2) * H + k], wb3 = w1[(H + j + 3) * H + k];
        #pragma unroll
        for (int n = 0; n < NB; n++) {
            float4 v = *reinterpret_cast<const float4*>(&hs[n][j]);
            a[n] = fmaf(v.x, wa0, a[n]); a[n] = fmaf(v.y, wa1, a[n]);
            a[n] = fmaf(v.z, wa2, a[n]); a[n] = fmaf(v.w, wa3, a[n]);
            b[n] = fmaf(v.x, wb0, b[n]); b[n] = fmaf(v.y, wb1, b[n]);
            b[n] = fmaf(v.z, wb2, b[n]); b[n] = fmaf(v.w, wb3, b[n]);
        }
    }
    #pragma unroll
    for (int n = 0; n < NB; n++) {
        A[(size_t)(i0 + n) * H + k] = a[n];
        B[(size_t)(i0 + n) * H + k] = b[n];
    }
}

// ---------------- edge kernel: warp-MMA, spill-free N-half pipeline ----------------
#define ASTRIDE 272   // bytes per A row (136 bf16, conflict-free ldmatrix)
#define SM_AHI   0
#define SM_ALO   34816
#define SM_EAS   69632
#define SM_MS    77824
#define SM_B2    86016
#define SM_CB    86528
#define SM_C2    87040
#define SM_C0    87552
#define SM_W1D   88064
#define SM_DIFF  88576
#define SM_DSQ   90112
#define SM_ROW   90624
#define SM_COL   91136
#define SM_SPART 91648
#define SMEM_EDGE_TOTAL 92160

extern "C" __global__ void __launch_bounds__(256, 2) edge_kernel(
    const int* __restrict__ row, const int* __restrict__ col,
    const float* __restrict__ x,
    const float* __restrict__ Ag, const float* __restrict__ Bg,
    const float* __restrict__ ea,
    const float* __restrict__ Mg, const float* __restrict__ c0g,
    const float* __restrict__ w1d,
    const float* __restrict__ b2, const float* __restrict__ cb,
    const float* __restrict__ c2,
    const uint4* __restrict__ w2f, const uint4* __restrict__ c1f,
    float* __restrict__ aggm, float* __restrict__ aggx) {
    extern __shared__ unsigned char smem[];
    const uint32_t smem_base = smem_u32(smem);
    int tid = threadIdx.x;
    int wid = tid >> 5, lane = tid & 31;
    int g = lane >> 2, tig = lane & 3;
    int k = tid & 127, eh = tid >> 7;
    int e0 = blockIdx.x * TILE_E;

    float* Ms    = (float*)(smem + SM_MS);
    float* EAs   = (float*)(smem + SM_EAS);
    float* B2s   = (float*)(smem + SM_B2);
    float* CBs   = (float*)(smem + SM_CB);
    float* C2s   = (float*)(smem + SM_C2);
    float* C0s   = (float*)(smem + SM_C0);
    float* W1Ds  = (float*)(smem + SM_W1D);
    float* DIFFs = (float*)(smem + SM_DIFF);
    float* DSQs  = (float*)(smem + SM_DSQ);
    int*   ROWs  = (int*)(smem + SM_ROW);
    int*   COLs  = (int*)(smem + SM_COL);
    float* SPARTs= (float*)(smem + SM_SPART);
    __nv_bfloat16* AHIb = (__nv_bfloat16*)(smem + SM_AHI);
    __nv_bfloat16* ALOb = (__nv_bfloat16*)(smem + SM_ALO);

    for (int i = tid; i < EDGE_IN * H; i += 256) Ms[i] = Mg[i];
    {
        const float4* src = (const float4*)(ea + (size_t)e0 * EDGE_IN);
        float4* dst = (float4*)EAs;
        for (int i = tid; i < TILE_E * EDGE_IN / 4; i += 256) dst[i] = src[i];
    }
    if (tid < H) {
        B2s[tid] = b2[tid]; CBs[tid] = cb[tid]; C2s[tid] = c2[tid];
        C0s[tid] = c0g[tid]; W1Ds[tid] = w1d[tid];
    }
    if (tid < TILE_E) {
        int e = e0 + tid;
        int r = row[e], c = col[e];
        ROWs[tid] = r; COLs[tid] = c;
        float dx = x[r * 3 + 0] - x[c * 3 + 0];
        float dy = x[r * 3 + 1] - x[c * 3 + 1];
        float dz = x[r * 3 + 2] - x[c * 3 + 2];
        DIFFs[tid * 3 + 0] = dx; DIFFs[tid * 3 + 1] = dy; DIFFs[tid * 3 + 2] = dz;
        DSQs[tid] = dx * dx + dy * dy + dz * dz;
    }
    __syncthreads();

    // build hidden tile: silu(A[r] + B[c] + c0 + dsq*w1d + ea@M), split bf16 hi/lo
    {
        float c0k = C0s[k], w1dk = W1Ds[k];
        #pragma unroll 2
        for (int e = eh; e < TILE_E; e += 2) {
            int r = ROWs[e], c = COLs[e];
            float pre = Ag[(size_t)r * H + k] + Bg[(size_t)c * H + k]
                      + c0k + DSQs[e] * w1dk;
            const float4* eav = (const float4*)&EAs[e * EDGE_IN];
            float4 v0 = eav[0], v1 = eav[1], v2 = eav[2], v3 = eav[3];
            pre = fmaf(v0.x, Ms[0 * H + k], pre);  pre = fmaf(v0.y, Ms[1 * H + k], pre);
            pre = fmaf(v0.z, Ms[2 * H + k], pre);  pre = fmaf(v0.w, Ms[3 * H + k], pre);
            pre = fmaf(v1.x, Ms[4 * H + k], pre);  pre = fmaf(v1.y, Ms[5 * H + k], pre);
            pre = fmaf(v1.z, Ms[6 * H + k], pre);  pre = fmaf(v1.w, Ms[7 * H + k], pre);
            pre = fmaf(v2.x, Ms[8 * H + k], pre);  pre = fmaf(v2.y, Ms[9 * H + k], pre);
            pre = fmaf(v2.z, Ms[10 * H + k], pre); pre = fmaf(v2.w, Ms[11 * H + k], pre);
            pre = fmaf(v3.x, Ms[12 * H + k], pre); pre = fmaf(v3.y, Ms[13 * H + k], pre);
            pre = fmaf(v3.z, Ms[14 * H + k], pre); pre = fmaf(v3.w, Ms[15 * H + k], pre);
            float hv = silu_f(pre);
            __nv_bfloat16 hh = __float2bfloat16(hv);
            __nv_bfloat16 hl = __float2bfloat16(hv - __bfloat162float(hh));
            AHIb[e * 136 + k] = hh;
            ALOb[e * 136 + k] = hl;
        }
    }
    __syncthreads();

    uint32_t aRowOff = (uint32_t)((16 * wid + (lane & 15)) * ASTRIDE + (lane >> 4) * 16);
    int e_lo = 16 * wid + g, e_hi = e_lo + 8;
    int r_lo = ROWs[e_lo], r_hi = ROWs[e_hi];

    // ---------------- GEMM1 in two N-halves (spill-free): d(32) live, m accumulates ------
    // D cols of nt pair (2j, 2j+1) == A-fragment k-tile j of GEMM2
    uint32_t mhi[8][4], mlo[8][4];
    #pragma unroll
    for (int nh = 0; nh < 2; nh++) {
        float d[8][4];
        #pragma unroll
        for (int j = 0; j < 8; j++) { d[j][0] = d[j][1] = d[j][2] = d[j][3] = 0.f; }
        #pragma unroll
        for (int kt = 0; kt < 8; kt++) {
            uint32_t ahi[4], alo[4];
            ldsm_x4(ahi, smem_base + SM_AHI + aRowOff + kt * 32);
            ldsm_x4(alo, smem_base + SM_ALO + aRowOff + kt * 32);
            const uint4* wk = w2f + kt * 512 + nh * 256 + lane;
            #pragma unroll
            for (int j = 0; j < 8; j++) {
                uint4 f = wk[j * 32];
                mma16816(d[j], ahi, f.x, f.y);
                mma16816(d[j], alo, f.x, f.y);
                mma16816(d[j], ahi, f.z, f.w);
            }
        }
        // conversion: m = silu(D + b2) -> GEMM2 A-frag k-tiles nh*4+jj; + v2 atomics
        #pragma unroll
        for (int jj = 0; jj < 4; jj++) {
            int jA = 2 * jj, jB = 2 * jj + 1;
            int kt2 = nh * 4 + jj;
            int chA = (nh * 8 + jA) * 8 + 2 * tig;
            int chB = (nh * 8 + jB) * 8 + 2 * tig;
            float bA0 = B2s[chA], bA1 = B2s[chA + 1];
            float bB0 = B2s[chB], bB1 = B2s[chB + 1];
            float mA00 = silu_f(d[jA][0] + bA0), mA01 = silu_f(d[jA][1] + bA1);
            float mA10 = silu_f(d[jA][2] + bA0), mA11 = silu_f(d[jA][3] + bA1);
            float mB00 = silu_f(d[jB][0] + bB0), mB01 = silu_f(d[jB][1] + bB1);
            float mB10 = silu_f(d[jB][2] + bB0), mB11 = silu_f(d[jB][3] + bB1);
            float hA00 = __bfloat162float(__float2bfloat16(mA00));
            float hA01 = __bfloat162float(__float2bfloat16(mA01));
            float hA10 = __bfloat162float(__float2bfloat16(mA10));
            float hA11 = __bfloat162float(__float2bfloat16(mA11));
            float hB00 = __bfloat162float(__float2bfloat16(mB00));
            float hB01 = __bfloat162float(__float2bfloat16(mB01));
            float hB10 = __bfloat162float(__float2bfloat16(mB10));
            float hB11 = __bfloat162float(__float2bfloat16(mB11));
            mhi[kt2][0] = pack2bf16(hA00, hA01); mlo[kt2][0] = pack2bf16(mA00 - hA00, mA01 - hA01);
            mhi[kt2][1] = pack2bf16(hA10, hA11); mlo[kt2][1] = pack2bf16(mA10 - hA10, mA11 - hA11);
            mhi[kt2][2] = pack2bf16(hB00, hB01); mlo[kt2][2] = pack2bf16(mB00 - hB00, mB01 - hB01);
            mhi[kt2][3] = pack2bf16(hB10, hB11); mlo[kt2][3] = pack2bf16(mB10 - hB10, mB11 - hB11);
            red_add_v2(aggm + (size_t)r_lo * H + chA, mA00, mA01);
            red_add_v2(aggm + (size_t)r_hi * H + chA, mA10, mA11);
            red_add_v2(aggm + (size_t)r_lo * H + chB, mB00, mB01);
            red_add_v2(aggm + (size_t)r_hi * H + chB, mB10, mB11);
        }
    }

    // ---------------- GEMM2: D2 = m @ c1, two N-halves, A-frags from registers ----------
    float s_lo = 0.f, s_hi = 0.f;
    #pragma unroll
    for (int nh = 0; nh < 2; nh++) {
        float d2[8][4];
        #pragma unroll
        for (int j2 = 0; j2 < 8; j2++) { d2[j2][0] = d2[j2][1] = d2[j2][2] = d2[j2][3] = 0.f; }
        #pragma unroll
        for (int kt = 0; kt < 8; kt++) {
            const uint4* wk = c1f + kt * 512 + (nh * 8) * 32 + lane;
            #pragma unroll
            for (int j2 = 0; j2 < 8; j2++) {
                uint4 f = wk[j2 * 32];
                mma16816(d2[j2], mhi[kt], f.x, f.y);
                mma16816(d2[j2], mlo[kt], f.x, f.y);
                mma16816(d2[j2], mhi[kt], f.z, f.w);
            }
        }
        #pragma unroll
        for (int j2 = 0; j2 < 8; j2++) {
            int ch0 = (nh * 8 + j2) * 8 + 2 * tig;
            float cb0 = CBs[ch0], cb1 = CBs[ch0 + 1];
            float cc0 = C2s[ch0], cc1 = C2s[ch0 + 1];
            s_lo = fmaf(silu_f(d2[j2][0] + cb0), cc0, s_lo);
            s_lo = fmaf(silu_f(d2[j2][1] + cb1), cc1, s_lo);
            s_hi = fmaf(silu_f(d2[j2][2] + cb0), cc0, s_hi);
            s_hi = fmaf(silu_f(d2[j2][3] + cb1), cc1, s_hi);
        }
    }
    s_lo += __shfl_xor_sync(0xffffffffu, s_lo, 1);
    s_lo += __shfl_xor_sync(0xffffffffu, s_lo, 2);
    s_hi += __shfl_xor_sync(0xffffffffu, s_hi, 1);
    s_hi += __shfl_xor_sync(0xffffffffu, s_hi, 2);
    if (tig == 0) {
        SPARTs[16 * wid + g] = s_lo;
        SPARTs[16 * wid + 8 + g] = s_hi;
    }
    __syncthreads();

    if (tid < TILE_E) {
        float wv = tanhf(SPARTs[tid]);
        float dist = sqrtf(DSQs[tid] + EPS_F);
        float inv = wv / (dist + EPS_F);
        int r = ROWs[tid];
        atomicAdd(&aggx[r * 3 + 0], DIFFs[tid * 3 + 0] * inv);
        atomicAdd(&aggx[r * 3 + 1], DIFFs[tid * 3 + 1] * inv);
        atomicAdd(&aggx[r * 3 + 2], DIFFs[tid * 3 + 2] * inv);
    }
}

// ---------------- per-layer node update, NB nodes per block ----------------
__global__ void __launch_bounds__(128) node_update_kernel(
    float* __restrict__ hf, const float* __restrict__ aggm,
    float* __restrict__ xb, const float* __restrict__ aggx,
    const float* __restrict__ mask,
    const float* __restrict__ n1, const float* __restrict__ nb1,
    const float* __restrict__ n2, const float* __restrict__ nb2) {
    __shared__ float ins[NB][2 * H];
    __shared__ float hid[NB][H];
    int i0 = blockIdx.x * NB, k = threadIdx.x;
    #pragma unroll
    for (int n = 0; n < NB; n++) {
        ins[n][k] = hf[(size_t)(i0 + n) * H + k];
        ins[n][H + k] = aggm[(size_t)(i0 + n) * H + k];
    }
    __syncthreads();
    float a[NB];
    {
        float nb = nb1[k];
        #pragma unroll
        for (int n = 0; n < NB; n++) a[n] = nb;
    }
    for (int j = 0; j < 2 * H; j += 4) {
        float w0 = n1[(j + 0) * H + k], w1v = n1[(j + 1) * H + k];
        float w2v = n1[(j + 2) * H + k], w3 = n1[(j + 3) * H + k];
        #pragma unroll
        for (int n = 0; n < NB; n++) {
            float4 v = *reinterpret_cast<const float4*>(&ins[n][j]);
            a[n] = fmaf(v.x, w0, a[n]); a[n] = fmaf(v.y, w1v, a[n]);
            a[n] = fmaf(v.z, w2v, a[n]); a[n] = fmaf(v.w, w3, a[n]);
        }
    }
    #pragma unroll
    for (int n = 0; n < NB; n++) hid[n][k] = silu_f(a[n]);
    __syncthreads();
    float b[NB];
    {
        float nb = nb2[k];
        #pragma unroll
        for (int n = 0; n < NB; n++) b[n] = nb;
    }
    for (int j = 0; j < H; j += 4) {
        float w0 = n2[(j + 0) * H + k], w1v = n2[(j + 1) * H + k];
        float w2v = n2[(j + 2) * H + k], w3 = n2[(j + 3) * H + k];
        #pragma unroll
        for (int n = 0; n < NB; n++) {
            float4 v = *reinterpret_cast<const float4*>(&hid[n][j]);
            b[n] = fmaf(v.x, w0, b[n]); b[n] = fmaf(v.y, w1v, b[n]);
            b[n] = fmaf(v.z, w2v, b[n]); b[n] = fmaf(v.w, w3, b[n]);
        }
    }
    #pragma unroll
    for (int n = 0; n < NB; n++)
        hf[(size_t)(i0 + n) * H + k] = ins[n][k] + b[n];
    if (k < 3 * NB) {
        int n = k / 3;
        xb[i0 * 3 + k] += aggx[i0 * 3 + k] * mask[i0 + n];
    }
}

// ---------------- final velocity ----------------
__global__ void v_kernel(const float* __restrict__ xb, const float* __restrict__ x_in,
                         const float* __restrict__ mask, float* __restrict__ out) {
    int idx = blockIdx.x * blockDim.x + threadIdx.x;
    if (idx < N_NODES * 3) {
        int i = idx / 3;
        out[idx] = (xb[idx] - x_in[idx]) * mask[i];
    }
}

extern "C" void kernel_launch(void* const* d_in, const int* in_sizes, int n_in,
                              void* d_out, int out_size) {
    const float* h        = (const float*)d_in[0];
    const float* x        = (const float*)d_in[1];
    const int*   ei       = (const int*)d_in[2];
    const float* ea       = (const float*)d_in[3];
    const float* t        = (const float*)d_in[4];
    const float* mask     = (const float*)d_in[5];
    const float* tw1      = (const float*)d_in[6];
    const float* tb1      = (const float*)d_in[7];
    const float* tw2      = (const float*)d_in[8];
    const float* tb2      = (const float*)d_in[9];
    const float* new_     = (const float*)d_in[10];
    const float* neb      = (const float*)d_in[11];
    const float* eew      = (const float*)d_in[12];
    const float* eeb      = (const float*)d_in[13];
    const float* ew1      = (const float*)d_in[14];
    const float* eb1      = (const float*)d_in[15];
    const float* ew2      = (const float*)d_in[16];
    const float* eb2      = (const float*)d_in[17];
    const float* cw1      = (const float*)d_in[18];
    const float* cb1      = (const float*)d_in[19];
    const float* cw2      = (const float*)d_in[20];
    const float* nw1      = (const float*)d_in[21];
    const float* nb1      = (const float*)d_in[22];
    const float* nw2      = (const float*)d_in[23];
    const float* nb2      = (const float*)d_in[24];
    float* out = (float*)d_out;

    float *hfeat, *Ab, *Bb, *xb, *aggm, *aggx, *Mb, *c0b;
    uint4 *w2f, *c1f;
    cudaGetSymbolAddress((void**)&hfeat, g_hfeat);
    cudaGetSymbolAddress((void**)&Ab,    g_A);
    cudaGetSymbolAddress((void**)&Bb,    g_B);
    cudaGetSymbolAddress((void**)&xb,    g_x);
    cudaGetSymbolAddress((void**)&aggm,  g_aggm);
    cudaGetSymbolAddress((void**)&aggx,  g_aggx);
    cudaGetSymbolAddress((void**)&Mb,    g_M);
    cudaGetSymbolAddress((void**)&c0b,   g_c0);
    cudaGetSymbolAddress((void**)&w2f,   g_w2f);
    cudaGetSymbolAddress((void**)&c1f,   g_c1f);

    cudaFuncSetAttribute(edge_kernel, cudaFuncAttributeMaxDynamicSharedMemorySize,
                         SMEM_EDGE_TOTAL);

    node_embed_kernel<<<N_NODES / NB, H>>>(h, new_, neb, t, tw1, tb1, tw2, tb2,
                                           x, hfeat, xb);
    prep_all_kernel<<<L_LAYERS + 256, H>>>(eew, eeb, ew1, eb1, ew2, cw1, Mb, c0b);

    for (int l = 0; l < L_LAYERS; l++) {
        const float* w1  = ew1 + (size_t)l * 385 * H;
        const float* b2  = eb2 + l * H;
        const float* cb  = cb1 + l * H;
        const float* c2  = cw2 + l * H;
        const float* n1  = nw1 + (size_t)l * 2 * H * H;
        const float* nb1l = nb1 + l * H;
        const float* n2  = nw2 + (size_t)l * H * H;
        const float* nb2l = nb2 + l * H;

        ab_kernel<<<N_NODES / NB, H>>>(hfeat, w1, Ab, Bb, aggm, aggx);
        edge_kernel<<<N_EDGES / TILE_E, 256, SMEM_EDGE_TOTAL>>>(
            ei, ei + N_EDGES, xb, Ab, Bb, ea, Mb + l * EDGE_IN * H, c0b + l * H,
            w1 + 256 * H, b2, cb, c2, w2f + l * 4096, c1f + l * 4096,
            aggm, aggx);
        node_update_kernel<<<N_NODES / NB, H>>>(hfeat, aggm, xb, aggx, mask,
                                                n1, nb1l, n2, nb2l);
    }
    v_kernel<<<(N_NODES * 3 + 127) / 128, 128>>>(xb, x, mask, out);
}

// round 10
// speedup vs baseline: 2.3717x; 1.0709x over previous
#include <cuda_runtime.h>
#include <cuda_bf16.h>
#include <math.h>
#include <stdint.h>

#define N_NODES 10000
#define N_EDGES 320000
#define H 128
#define NODE_IN 64
#define EDGE_IN 16
#define L_LAYERS 4
#define EPS_F 1e-8f
#define TILE_E 128
#define NB 8

// ---------------- scratch (device globals; no allocation allowed) ----------------
__device__ float g_hfeat[N_NODES * H];
__device__ float g_A[N_NODES * H];
__device__ float g_B[N_NODES * H];
__device__ float g_x[N_NODES * 3];
__device__ float g_aggm[N_NODES * H];
__device__ float g_aggx[N_NODES * 3];
__device__ float g_M[L_LAYERS * EDGE_IN * H];   // folded low-rank edge weights
__device__ float g_c0[L_LAYERS * H];            // folded biases
// B fragments in MMA order: [layer][kt(8)][nt(16)][lane(32)] -> uint4 {bhi0,bhi1,blo0,blo1}
__device__ uint4 g_w2f[L_LAYERS * 4096];
__device__ uint4 g_c1f[L_LAYERS * 4096];

__device__ __forceinline__ float silu_f(float v) {
    return v / (1.0f + __expf(-v));
}

__device__ __forceinline__ uint32_t smem_u32(const void* p) {
    uint32_t a;
    asm("{ .reg .u64 t; cvta.to.shared.u64 t, %1; cvt.u32.u64 %0, t; }" : "=r"(a) : "l"(p));
    return a;
}

__device__ __forceinline__ void ldsm_x4(uint32_t* r, uint32_t addr) {
    asm volatile("ldmatrix.sync.aligned.m8n8.x4.shared.b16 {%0,%1,%2,%3}, [%4];"
        : "=r"(r[0]), "=r"(r[1]), "=r"(r[2]), "=r"(r[3]) : "r"(addr));
}
__device__ __forceinline__ void mma16816(float* d, const uint32_t* a, uint32_t b0, uint32_t b1) {
    asm volatile("mma.sync.aligned.m16n8k16.row.col.f32.bf16.bf16.f32 "
        "{%0,%1,%2,%3}, {%4,%5,%6,%7}, {%8,%9}, {%0,%1,%2,%3};"
        : "+f"(d[0]), "+f"(d[1]), "+f"(d[2]), "+f"(d[3])
        : "r"(a[0]), "r"(a[1]), "r"(a[2]), "r"(a[3]), "r"(b0), "r"(b1));
}
__device__ __forceinline__ void red_add_v2(float* addr, float a, float b) {
    asm volatile("red.global.add.v2.f32 [%0], {%1, %2};"
        :: "l"(addr), "f"(a), "f"(b) : "memory");
}
__device__ __forceinline__ uint32_t pack2bf16(float a, float b) {
    uint32_t ua = (uint32_t)__bfloat16_as_ushort(__float2bfloat16(a));
    uint32_t ub = (uint32_t)__bfloat16_as_ushort(__float2bfloat16(b));
    return ua | (ub << 16);
}

// ---------------- node embedding (t-embedding fused in) + x init ----------------
__global__ void __launch_bounds__(128) node_embed_kernel(
    const float* __restrict__ h, const float* __restrict__ W, const float* __restrict__ b,
    const float* __restrict__ t,
    const float* __restrict__ tw1, const float* __restrict__ tb1,
    const float* __restrict__ tw2, const float* __restrict__ tb2,
    const float* __restrict__ x_in,
    float* __restrict__ hf, float* __restrict__ xb) {
    __shared__ float hs[NB][NODE_IN];
    __shared__ float h1[H];
    int i0 = blockIdx.x * NB, k = threadIdx.x;
    h1[k] = silu_f(t[0] * tw1[k] + tb1[k]);
    {
        const float* hsrc = h + (size_t)i0 * NODE_IN;
        for (int i = k; i < NB * NODE_IN; i += 128) (&hs[0][0])[i] = hsrc[i];
    }
    __syncthreads();
    float te = tb2[k] + b[k];
    for (int j = 0; j < H; j += 4) {
        float4 v = *reinterpret_cast<const float4*>(&h1[j]);
        te = fmaf(v.x, tw2[(j + 0) * H + k], te);
        te = fmaf(v.y, tw2[(j + 1) * H + k], te);
        te = fmaf(v.z, tw2[(j + 2) * H + k], te);
        te = fmaf(v.w, tw2[(j + 3) * H + k], te);
    }
    float acc[NB];
    #pragma unroll
    for (int n = 0; n < NB; n++) acc[n] = te;
    for (int j = 0; j < NODE_IN; j += 4) {
        float w0 = W[(j + 0) * H + k], w1v = W[(j + 1) * H + k];
        float w2v = W[(j + 2) * H + k], w3 = W[(j + 3) * H + k];
        #pragma unroll
        for (int n = 0; n < NB; n++) {
            float4 v = *reinterpret_cast<const float4*>(&hs[n][j]);
            acc[n] = fmaf(v.x, w0, acc[n]); acc[n] = fmaf(v.y, w1v, acc[n]);
            acc[n] = fmaf(v.z, w2v, acc[n]); acc[n] = fmaf(v.w, w3, acc[n]);
        }
    }
    #pragma unroll
    for (int n = 0; n < NB; n++) hf[(size_t)(i0 + n) * H + k] = acc[n];
    if (k < 3 * NB) xb[i0 * 3 + k] = x_in[i0 * 3 + k];
}

// ---------------- fused prep: fold M/c0 (blocks 0..3) + w2/c1 MMA frags (blocks 4..259) ----
__global__ void prep_all_kernel(const float* __restrict__ eew, const float* __restrict__ eeb,
                                const float* __restrict__ ew1, const float* __restrict__ eb1,
                                const float* __restrict__ ew2, const float* __restrict__ cw1,
                                float* __restrict__ M, float* __restrict__ c0) {
    int k = threadIdx.x;
    if (blockIdx.x < L_LAYERS) {
        __shared__ float es[EDGE_IN][H];
        __shared__ float ebs[H];
        int l = blockIdx.x;
        const float* w1c = ew1 + (size_t)l * 385 * H + 257 * H;
        const float* b1 = eb1 + l * H;
        #pragma unroll
        for (int i = 0; i < EDGE_IN; i++) es[i][k] = eew[i * H + k];
        ebs[k] = eeb[k];
        __syncthreads();
        float m[EDGE_IN];
        #pragma unroll
        for (int i = 0; i < EDGE_IN; i++) m[i] = 0.f;
        float c = b1[k];
        for (int j = 0; j < H; j++) {
            float w = w1c[j * H + k];
            c = fmaf(ebs[j], w, c);
            #pragma unroll
            for (int i = 0; i < EDGE_IN; i++) m[i] = fmaf(es[i][j], w, m[i]);
        }
        #pragma unroll
        for (int i = 0; i < EDGE_IN; i++) M[l * EDGE_IN * H + i * H + k] = m[i];
        c0[l * H + k] = c;
    } else {
        int idx2 = blockIdx.x - L_LAYERS;
        int mat = idx2 >> 7;
        int l = (idx2 >> 5) & 3;
        int idx = (idx2 & 31) * 128 + k;
        const float* W = (mat == 0) ? (ew2 + (size_t)l * H * H) : (cw1 + (size_t)l * H * H);
        uint4* out = ((mat == 0) ? g_w2f : g_c1f) + l * 4096;
        int kt = idx >> 9;
        int nt = (idx >> 5) & 15;
        int lane = idx & 31;
        int n = nt * 8 + (lane >> 2);
        int k0 = kt * 16 + 2 * (lane & 3);
        float v00 = W[(k0 + 0) * H + n], v01 = W[(k0 + 1) * H + n];
        float v10 = W[(k0 + 8) * H + n], v11 = W[(k0 + 9) * H + n];
        float h00 = __bfloat162float(__float2bfloat16(v00));
        float h01 = __bfloat162float(__float2bfloat16(v01));
        float h10 = __bfloat162float(__float2bfloat16(v10));
        float h11 = __bfloat162float(__float2bfloat16(v11));
        uint4 f;
        f.x = pack2bf16(h00, h01);
        f.y = pack2bf16(h10, h11);
        f.z = pack2bf16(v00 - h00, v01 - h01);
        f.w = pack2bf16(v10 - h10, v11 - h11);
        out[idx] = f;
    }
}

// ---------------- per-layer: A/B projections, NB nodes per block; zero agg ----------------
__global__ void __launch_bounds__(128) ab_kernel(
    const float* __restrict__ hf, const float* __restrict__ w1,
    float* __restrict__ A, float* __restrict__ B,
    float* __restrict__ aggm, float* __restrict__ aggx) {
    __shared__ float hs[NB][H];
    int i0 = blockIdx.x * NB, k = threadIdx.x;
    #pragma unroll
    for (int n = 0; n < NB; n++) {
        hs[n][k] = hf[(size_t)(i0 + n) * H + k];
        aggm[(size_t)(i0 + n) * H + k] = 0.f;
    }
    if (k < 3 * NB) aggx[i0 * 3 + k] = 0.f;
    __syncthreads();
    float a[NB], b[NB];
    #pragma unroll
    for (int n = 0; n < NB; n++) { a[n] = 0.f; b[n] = 0.f; }
    for (int j = 0; j < H; j += 4) {
        float wa0 = w1[(j + 0) * H + k], wa1 = w1[(j + 1) * H + k];
        float wa2 = w1[(j + 2) * H + k], wa3 = w1[(j + 3) * H + k];
        float wb0 = w1[(H + j + 0) * H + k], wb1 = w1[(H + j + 1) * H + k];
        float wb2 = w1[(H + j + 2) * H + k], wb3 = w1[(H + j + 3) * H + k];
        #pragma unroll
        for (int n = 0; n < NB; n++) {
            float4 v = *reinterpret_cast<const float4*>(&hs[n][j]);
            a[n] = fmaf(v.x, wa0, a[n]); a[n] = fmaf(v.y, wa1, a[n]);
            a[n] = fmaf(v.z, wa2, a[n]); a[n] = fmaf(v.w, wa3, a[n]);
            b[n] = fmaf(v.x, wb0, b[n]); b[n] = fmaf(v.y, wb1, b[n]);
            b[n] = fmaf(v.z, wb2, b[n]); b[n] = fmaf(v.w, wb3, b[n]);
        }
    }
    #pragma unroll
    for (int n = 0; n < NB; n++) {
        A[(size_t)(i0 + n) * H + k] = a[n];
        B[(size_t)(i0 + n) * H + k] = b[n];
    }
}

// ---------------- edge kernel: warp-MMA, smem-m, 3 CTAs/SM ----------------
#define ASTRIDE 272   // bytes per A row (136 bf16, conflict-free ldmatrix)
#define SM_AHI   0
#define SM_ALO   34816
#define SM_B2    69632
#define SM_CB    70144
#define SM_C2    70656
#define SM_C0    71168
#define SM_W1D   71680
#define SM_DIFF  72192
#define SM_DSQ   73728
#define SM_ROW   74240
#define SM_COL   74752
#define SM_SPART 75264
#define SMEM_EDGE_TOTAL 75776

extern "C" __global__ void __launch_bounds__(256, 3) edge_kernel(
    const int* __restrict__ row, const int* __restrict__ col,
    const float* __restrict__ x,
    const float* __restrict__ Ag, const float* __restrict__ Bg,
    const float* __restrict__ ea,
    const float* __restrict__ Mg, const float* __restrict__ c0g,
    const float* __restrict__ w1d,
    const float* __restrict__ b2, const float* __restrict__ cb,
    const float* __restrict__ c2,
    const uint4* __restrict__ w2f, const uint4* __restrict__ c1f,
    float* __restrict__ aggm, float* __restrict__ aggx) {
    extern __shared__ unsigned char smem[];
    const uint32_t smem_base = smem_u32(smem);
    int tid = threadIdx.x;
    int wid = tid >> 5, lane = tid & 31;
    int g = lane >> 2, tig = lane & 3;
    int k = tid & 127, eh = tid >> 7;
    int e0 = blockIdx.x * TILE_E;

    float* B2s   = (float*)(smem + SM_B2);
    float* CBs   = (float*)(smem + SM_CB);
    float* C2s   = (float*)(smem + SM_C2);
    float* C0s   = (float*)(smem + SM_C0);
    float* W1Ds  = (float*)(smem + SM_W1D);
    float* DIFFs = (float*)(smem + SM_DIFF);
    float* DSQs  = (float*)(smem + SM_DSQ);
    int*   ROWs  = (int*)(smem + SM_ROW);
    int*   COLs  = (int*)(smem + SM_COL);
    float* SPARTs= (float*)(smem + SM_SPART);
    __nv_bfloat16* AHIb = (__nv_bfloat16*)(smem + SM_AHI);
    __nv_bfloat16* ALOb = (__nv_bfloat16*)(smem + SM_ALO);

    if (tid < H) {
        B2s[tid] = b2[tid]; CBs[tid] = cb[tid]; C2s[tid] = c2[tid];
        C0s[tid] = c0g[tid]; W1Ds[tid] = w1d[tid];
    }
    if (tid < TILE_E) {
        int e = e0 + tid;
        int r = row[e], c = col[e];
        ROWs[tid] = r; COLs[tid] = c;
        float dx = x[r * 3 + 0] - x[c * 3 + 0];
        float dy = x[r * 3 + 1] - x[c * 3 + 1];
        float dz = x[r * 3 + 2] - x[c * 3 + 2];
        DIFFs[tid * 3 + 0] = dx; DIFFs[tid * 3 + 1] = dy; DIFFs[tid * 3 + 2] = dz;
        DSQs[tid] = dx * dx + dy * dy + dz * dz;
    }
    __syncthreads();

    // build hidden tile: silu(A[r] + B[c] + c0 + dsq*w1d + ea@M), split bf16 hi/lo
    // M held in registers (phase-local); ea read as warp-uniform float4 (L1 broadcast)
    {
        float Mr[EDGE_IN];
        #pragma unroll
        for (int i = 0; i < EDGE_IN; i++) Mr[i] = Mg[i * H + k];
        float c0k = C0s[k], w1dk = W1Ds[k];
        #pragma unroll 2
        for (int e = eh; e < TILE_E; e += 2) {
            int r = ROWs[e], c = COLs[e];
            float pre = Ag[(size_t)r * H + k] + Bg[(size_t)c * H + k]
                      + c0k + DSQs[e] * w1dk;
            const float4* eav = (const float4*)(ea + (size_t)(e0 + e) * EDGE_IN);
            float4 v0 = eav[0], v1 = eav[1], v2 = eav[2], v3 = eav[3];
            pre = fmaf(v0.x, Mr[0], pre);  pre = fmaf(v0.y, Mr[1], pre);
            pre = fmaf(v0.z, Mr[2], pre);  pre = fmaf(v0.w, Mr[3], pre);
            pre = fmaf(v1.x, Mr[4], pre);  pre = fmaf(v1.y, Mr[5], pre);
            pre = fmaf(v1.z, Mr[6], pre);  pre = fmaf(v1.w, Mr[7], pre);
            pre = fmaf(v2.x, Mr[8], pre);  pre = fmaf(v2.y, Mr[9], pre);
            pre = fmaf(v2.z, Mr[10], pre); pre = fmaf(v2.w, Mr[11], pre);
            pre = fmaf(v3.x, Mr[12], pre); pre = fmaf(v3.y, Mr[13], pre);
            pre = fmaf(v3.z, Mr[14], pre); pre = fmaf(v3.w, Mr[15], pre);
            float hv = silu_f(pre);
            __nv_bfloat16 hh = __float2bfloat16(hv);
            __nv_bfloat16 hl = __float2bfloat16(hv - __bfloat162float(hh));
            AHIb[e * 136 + k] = hh;
            ALOb[e * 136 + k] = hl;
        }
    }
    __syncthreads();

    uint32_t aRowOff = (uint32_t)((16 * wid + (lane & 15)) * ASTRIDE + (lane >> 4) * 16);
    int e_lo = 16 * wid + g, e_hi = e_lo + 8;
    int r_lo = ROWs[e_lo], r_hi = ROWs[e_hi];

    // ---------------- GEMM1: D = hidden @ w2 (full width) ----------------
    {
        float d[16][4];
        #pragma unroll
        for (int nt = 0; nt < 16; nt++) { d[nt][0] = d[nt][1] = d[nt][2] = d[nt][3] = 0.f; }
        #pragma unroll
        for (int kt = 0; kt < 8; kt++) {
            uint32_t ahi[4], alo[4];
            ldsm_x4(ahi, smem_base + SM_AHI + aRowOff + kt * 32);
            ldsm_x4(alo, smem_base + SM_ALO + aRowOff + kt * 32);
            const uint4* wk = w2f + kt * 512 + lane;
            #pragma unroll
            for (int nt = 0; nt < 16; nt++) {
                uint4 f = wk[nt * 32];
                mma16816(d[nt], ahi, f.x, f.y);
                mma16816(d[nt], alo, f.x, f.y);
                mma16816(d[nt], ahi, f.z, f.w);
            }
        }

        // conversion: m = silu(D + b2) -> smem (own rows, hi->AHI, lo->ALO) + v2 atomics
        #pragma unroll
        for (int nt = 0; nt < 16; nt++) {
            int ch0 = nt * 8 + 2 * tig;
            float b0 = B2s[ch0], b1v = B2s[ch0 + 1];
            float m00 = silu_f(d[nt][0] + b0);
            float m01 = silu_f(d[nt][1] + b1v);
            float m10 = silu_f(d[nt][2] + b0);
            float m11 = silu_f(d[nt][3] + b1v);
            float h00 = __bfloat162float(__float2bfloat16(m00));
            float h01 = __bfloat162float(__float2bfloat16(m01));
            float h10 = __bfloat162float(__float2bfloat16(m10));
            float h11 = __bfloat162float(__float2bfloat16(m11));
            *(uint32_t*)(smem + SM_AHI + e_lo * ASTRIDE + ch0 * 2) = pack2bf16(h00, h01);
            *(uint32_t*)(smem + SM_AHI + e_hi * ASTRIDE + ch0 * 2) = pack2bf16(h10, h11);
            *(uint32_t*)(smem + SM_ALO + e_lo * ASTRIDE + ch0 * 2) = pack2bf16(m00 - h00, m01 - h01);
            *(uint32_t*)(smem + SM_ALO + e_hi * ASTRIDE + ch0 * 2) = pack2bf16(m10 - h10, m11 - h11);
            red_add_v2(aggm + (size_t)r_lo * H + ch0, m00, m01);
            red_add_v2(aggm + (size_t)r_hi * H + ch0, m10, m11);
        }
    }
    __syncwarp();   // m rows are warp-private; warp-local ordering suffices

    // ---------------- GEMM2: D2 = m @ c1, two N-halves, A via ldmatrix ----------------
    float s_lo = 0.f, s_hi = 0.f;
    #pragma unroll
    for (int nh = 0; nh < 2; nh++) {
        float d2[8][4];
        #pragma unroll
        for (int j2 = 0; j2 < 8; j2++) { d2[j2][0] = d2[j2][1] = d2[j2][2] = d2[j2][3] = 0.f; }
        #pragma unroll
        for (int kt = 0; kt < 8; kt++) {
            uint32_t ahi[4], alo[4];
            ldsm_x4(ahi, smem_base + SM_AHI + aRowOff + kt * 32);
            ldsm_x4(alo, smem_base + SM_ALO + aRowOff + kt * 32);
            const uint4* wk = c1f + kt * 512 + nh * 256 + lane;
            #pragma unroll
            for (int j2 = 0; j2 < 8; j2++) {
                uint4 f = wk[j2 * 32];
                mma16816(d2[j2], ahi, f.x, f.y);
                mma16816(d2[j2], alo, f.x, f.y);
                mma16816(d2[j2], ahi, f.z, f.w);
            }
        }
        #pragma unroll
        for (int j2 = 0; j2 < 8; j2++) {
            int ch0 = (nh * 8 + j2) * 8 + 2 * tig;
            float cb0 = CBs[ch0], cb1 = CBs[ch0 + 1];
            float cc0 = C2s[ch0], cc1 = C2s[ch0 + 1];
            s_lo = fmaf(silu_f(d2[j2][0] + cb0), cc0, s_lo);
            s_lo = fmaf(silu_f(d2[j2][1] + cb1), cc1, s_lo);
            s_hi = fmaf(silu_f(d2[j2][2] + cb0), cc0, s_hi);
            s_hi = fmaf(silu_f(d2[j2][3] + cb1), cc1, s_hi);
        }
    }
    s_lo += __shfl_xor_sync(0xffffffffu, s_lo, 1);
    s_lo += __shfl_xor_sync(0xffffffffu, s_lo, 2);
    s_hi += __shfl_xor_sync(0xffffffffu, s_hi, 1);
    s_hi += __shfl_xor_sync(0xffffffffu, s_hi, 2);
    if (tig == 0) {
        SPARTs[16 * wid + g] = s_lo;
        SPARTs[16 * wid + 8 + g] = s_hi;
    }
    __syncthreads();

    if (tid < TILE_E) {
        float wv = tanhf(SPARTs[tid]);
        float dist = sqrtf(DSQs[tid] + EPS_F);
        float inv = wv / (dist + EPS_F);
        int r = ROWs[tid];
        atomicAdd(&aggx[r * 3 + 0], DIFFs[tid * 3 + 0] * inv);
        atomicAdd(&aggx[r * 3 + 1], DIFFs[tid * 3 + 1] * inv);
        atomicAdd(&aggx[r * 3 + 2], DIFFs[tid * 3 + 2] * inv);
    }
}

// ---------------- per-layer node update, NB nodes per block ----------------
__global__ void __launch_bounds__(128) node_update_kernel(
    float* __restrict__ hf, const float* __restrict__ aggm,
    float* __restrict__ xb, const float* __restrict__ aggx,
    const float* __restrict__ mask,
    const float* __restrict__ n1, const float* __restrict__ nb1,
    const float* __restrict__ n2, const float* __restrict__ nb2) {
    __shared__ float ins[NB][2 * H];
    __shared__ float hid[NB][H];
    int i0 = blockIdx.x * NB, k = threadIdx.x;
    #pragma unroll
    for (int n = 0; n < NB; n++) {
        ins[n][k] = hf[(size_t)(i0 + n) * H + k];
        ins[n][H + k] = aggm[(size_t)(i0 + n) * H + k];
    }
    __syncthreads();
    float a[NB];
    {
        float nb = nb1[k];
        #pragma unroll
        for (int n = 0; n < NB; n++) a[n] = nb;
    }
    for (int j = 0; j < 2 * H; j += 4) {
        float w0 = n1[(j + 0) * H + k], w1v = n1[(j + 1) * H + k];
        float w2v = n1[(j + 2) * H + k], w3 = n1[(j + 3) * H + k];
        #pragma unroll
        for (int n = 0; n < NB; n++) {
            float4 v = *reinterpret_cast<const float4*>(&ins[n][j]);
            a[n] = fmaf(v.x, w0, a[n]); a[n] = fmaf(v.y, w1v, a[n]);
            a[n] = fmaf(v.z, w2v, a[n]); a[n] = fmaf(v.w, w3, a[n]);
        }
    }
    #pragma unroll
    for (int n = 0; n < NB; n++) hid[n][k] = silu_f(a[n]);
    __syncthreads();
    float b[NB];
    {
        float nb = nb2[k];
        #pragma unroll
        for (int n = 0; n < NB; n++) b[n] = nb;
    }
    for (int j = 0; j < H; j += 4) {
        float w0 = n2[(j + 0) * H + k], w1v = n2[(j + 1) * H + k];
        float w2v = n2[(j + 2) * H + k], w3 = n2[(j + 3) * H + k];
        #pragma unroll
        for (int n = 0; n < NB; n++) {
            float4 v = *reinterpret_cast<const float4*>(&hid[n][j]);
            b[n] = fmaf(v.x, w0, b[n]); b[n] = fmaf(v.y, w1v, b[n]);
            b[n] = fmaf(v.z, w2v, b[n]); b[n] = fmaf(v.w, w3, b[n]);
        }
    }
    #pragma unroll
    for (int n = 0; n < NB; n++)
        hf[(size_t)(i0 + n) * H + k] = ins[n][k] + b[n];
    if (k < 3 * NB) {
        int n = k / 3;
        xb[i0 * 3 + k] += aggx[i0 * 3 + k] * mask[i0 + n];
    }
}

// ---------------- final velocity ----------------
__global__ void v_kernel(const float* __restrict__ xb, const float* __restrict__ x_in,
                         const float* __restrict__ mask, float* __restrict__ out) {
    int idx = blockIdx.x * blockDim.x + threadIdx.x;
    if (idx < N_NODES * 3) {
        int i = idx / 3;
        out[idx] = (xb[idx] - x_in[idx]) * mask[i];
    }
}

extern "C" void kernel_launch(void* const* d_in, const int* in_sizes, int n_in,
                              void* d_out, int out_size) {
    const float* h        = (const float*)d_in[0];
    const float* x        = (const float*)d_in[1];
    const int*   ei       = (const int*)d_in[2];
    const float* ea       = (const float*)d_in[3];
    const float* t        = (const float*)d_in[4];
    const float* mask     = (const float*)d_in[5];
    const float* tw1      = (const float*)d_in[6];
    const float* tb1      = (const float*)d_in[7];
    const float* tw2      = (const float*)d_in[8];
    const float* tb2      = (const float*)d_in[9];
    const float* new_     = (const float*)d_in[10];
    const float* neb      = (const float*)d_in[11];
    const float* eew      = (const float*)d_in[12];
    const float* eeb      = (const float*)d_in[13];
    const float* ew1      = (const float*)d_in[14];
    const float* eb1      = (const float*)d_in[15];
    const float* ew2      = (const float*)d_in[16];
    const float* eb2      = (const float*)d_in[17];
    const float* cw1      = (const float*)d_in[18];
    const float* cb1      = (const float*)d_in[19];
    const float* cw2      = (const float*)d_in[20];
    const float* nw1      = (const float*)d_in[21];
    const float* nb1      = (const float*)d_in[22];
    const float* nw2      = (const float*)d_in[23];
    const float* nb2      = (const float*)d_in[24];
    float* out = (float*)d_out;

    float *hfeat, *Ab, *Bb, *xb, *aggm, *aggx, *Mb, *c0b;
    uint4 *w2f, *c1f;
    cudaGetSymbolAddress((void**)&hfeat, g_hfeat);
    cudaGetSymbolAddress((void**)&Ab,    g_A);
    cudaGetSymbolAddress((void**)&Bb,    g_B);
    cudaGetSymbolAddress((void**)&xb,    g_x);
    cudaGetSymbolAddress((void**)&aggm,  g_aggm);
    cudaGetSymbolAddress((void**)&aggx,  g_aggx);
    cudaGetSymbolAddress((void**)&Mb,    g_M);
    cudaGetSymbolAddress((void**)&c0b,   g_c0);
    cudaGetSymbolAddress((void**)&w2f,   g_w2f);
    cudaGetSymbolAddress((void**)&c1f,   g_c1f);

    cudaFuncSetAttribute(edge_kernel, cudaFuncAttributeMaxDynamicSharedMemorySize,
                         SMEM_EDGE_TOTAL);

    node_embed_kernel<<<N_NODES / NB, H>>>(h, new_, neb, t, tw1, tb1, tw2, tb2,
                                           x, hfeat, xb);
    prep_all_kernel<<<L_LAYERS + 256, H>>>(eew, eeb, ew1, eb1, ew2, cw1, Mb, c0b);

    for (int l = 0; l < L_LAYERS; l++) {
        const float* w1  = ew1 + (size_t)l * 385 * H;
        const float* b2  = eb2 + l * H;
        const float* cb  = cb1 + l * H;
        const float* c2  = cw2 + l * H;
        const float* n1  = nw1 + (size_t)l * 2 * H * H;
        const float* nb1l = nb1 + l * H;
        const float* n2  = nw2 + (size_t)l * H * H;
        const float* nb2l = nb2 + l * H;

        ab_kernel<<<N_NODES / NB, H>>>(hfeat, w1, Ab, Bb, aggm, aggx);
        edge_kernel<<<N_EDGES / TILE_E, 256, SMEM_EDGE_TOTAL>>>(
            ei, ei + N_EDGES, xb, Ab, Bb, ea, Mb + l * EDGE_IN * H, c0b + l * H,
            w1 + 256 * H, b2, cb, c2, w2f + l * 4096, c1f + l * 4096,
            aggm, aggx);
        node_update_kernel<<<N_NODES / NB, H>>>(hfeat, aggm, xb, aggx, mask,
                                                n1, nb1l, n2, nb2l);
    }
    v_kernel<<<(N_NODES * 3 + 127) / 128, 128>>>(xb, x, mask, out);
}